// round 12
// baseline (speedup 1.0000x reference)
#include <cuda_runtime.h>
#include <cuda_bf16.h>
#include <cstdint>

#define LSEQ 2048
#define BATCH 8
// 1/sqrt(512)
#define ATT_SCALE 0.044194173824159216f

// fp32 conv outputs
__device__ float g_q[BATCH * 512 * LSEQ];
__device__ float g_k[BATCH * 512 * LSEQ];
__device__ float g_v[BATCH * 512 * LSEQ];
// conv operand staging (split bf16)
__device__ uint4 g_w_hi4[3 * 512 * 1536 / 8];      // [conv][co][k][ci]
__device__ uint4 g_w_lo4[3 * 512 * 1536 / 8];
__device__ uint4 g_xt_hi4[BATCH * LSEQ * 512 / 8]; // [b][l][ci]
__device__ uint4 g_xt_lo4[BATCH * LSEQ * 512 / 8];
// attention operand staging (split bf16)
__device__ uint4 g_qt_hi4[64 * LSEQ * 64 / 8];     // [bh][l][d]
__device__ uint4 g_qt_lo4[64 * LSEQ * 64 / 8];
__device__ uint4 g_kt_hi4[64 * LSEQ * 64 / 8];     // [bh][l][d]
__device__ uint4 g_kt_lo4[64 * LSEQ * 64 / 8];
__device__ uint4 g_vt_hi4[64 * 64 * LSEQ / 8];     // [bh][d][l]
__device__ uint4 g_vt_lo4[64 * 64 * LSEQ / 8];
#define W_HI ((__nv_bfloat16*)g_w_hi4)
#define W_LO ((__nv_bfloat16*)g_w_lo4)
#define XT_HI ((__nv_bfloat16*)g_xt_hi4)
#define XT_LO ((__nv_bfloat16*)g_xt_lo4)
#define QT_HI ((__nv_bfloat16*)g_qt_hi4)
#define QT_LO ((__nv_bfloat16*)g_qt_lo4)
#define KT_HI ((__nv_bfloat16*)g_kt_hi4)
#define KT_LO ((__nv_bfloat16*)g_kt_lo4)
#define VT_HI ((__nv_bfloat16*)g_vt_hi4)
#define VT_LO ((__nv_bfloat16*)g_vt_lo4)

__device__ __forceinline__ uint32_t smem_u32(const void* p) {
    uint32_t a;
    asm("{ .reg .u64 t; cvta.to.shared.u64 t, %1; cvt.u32.u64 %0, t; }"
        : "=r"(a) : "l"(p));
    return a;
}
#define CPA(dst, src) \
    asm volatile("cp.async.ca.shared.global [%0], [%1], 16;" \
                 :: "r"(dst), "l"(src))
#define CPA_Z(dst, src, sz) \
    asm volatile("cp.async.ca.shared.global [%0], [%1], 16, %2;" \
                 :: "r"(dst), "l"(src), "r"(sz))
#define CPC()  asm volatile("cp.async.commit_group;")
#define CPW0() asm volatile("cp.async.wait_group 0;")

__device__ __forceinline__ void split2(float f, __nv_bfloat16& h, __nv_bfloat16& l) {
    h = __float2bfloat16_rn(f);
    l = __float2bfloat16_rn(f - __bfloat162float(h));
}
__device__ __forceinline__ uint32_t cvt_bf16x2(float f1, float f0) {
    uint32_t r;
    asm("cvt.rn.bf16x2.f32 %0, %1, %2;" : "=r"(r) : "f"(f1), "f"(f0));
    return r;
}
__device__ __forceinline__ void split_pack(float f1, float f0,
                                           uint32_t& h, uint32_t& l) {
    h = cvt_bf16x2(f1, f0);
    float h0 = __uint_as_float(h << 16);
    float h1 = __uint_as_float(h & 0xffff0000u);
    l = cvt_bf16x2(f1 - h1, f0 - h0);
}
__device__ __forceinline__ void mma_bf16(float acc[4], const uint32_t a[4],
                                         const uint32_t b[2])
{
    asm volatile(
        "mma.sync.aligned.m16n8k16.row.col.f32.bf16.bf16.f32 "
        "{%0,%1,%2,%3}, {%4,%5,%6,%7}, {%8,%9}, {%0,%1,%2,%3};\n"
        : "+f"(acc[0]), "+f"(acc[1]), "+f"(acc[2]), "+f"(acc[3])
        : "r"(a[0]), "r"(a[1]), "r"(a[2]), "r"(a[3]), "r"(b[0]), "r"(b[1]));
}

// ---------------------------------------------------------------------------
// w[co][ci][k] fp32 -> w_hi/lo[conv][co][k][ci] bf16
// ---------------------------------------------------------------------------
__global__ void __launch_bounds__(256) split_w_kernel(
    const float* __restrict__ w0, const float* __restrict__ w1,
    const float* __restrict__ w2)
{
    const int conv = blockIdx.y;
    const float* w = (conv == 0) ? w0 : (conv == 1) ? w1 : w2;
    int idx = blockIdx.x * 256 + threadIdx.x;
    int co = idx / 1536, r = idx - co * 1536;
    int kk = r >> 9, ci = r & 511;
    float f = w[(size_t)co * 1536 + ci * 3 + kk];
    __nv_bfloat16 h, l;
    split2(f, h, l);
    size_t o = (size_t)conv * 786432 + idx;
    W_HI[o] = h;
    W_LO[o] = l;
}

// ---------------------------------------------------------------------------
// x[b][ci][l] fp32 -> xt_hi/lo[b][l][ci] bf16, 32x32 smem transpose
// ---------------------------------------------------------------------------
__global__ void __launch_bounds__(256) split_x_kernel(const float* __restrict__ x)
{
    __shared__ float t[32][33];
    const int b = blockIdx.z, c0 = blockIdx.y * 32, l0 = blockIdx.x * 32;
    const int tx = threadIdx.x & 31, ty = threadIdx.x >> 5;
#pragma unroll
    for (int r = 0; r < 32; r += 8)
        t[ty + r][tx] = x[((size_t)b * 512 + c0 + ty + r) * LSEQ + l0 + tx];
    __syncthreads();
#pragma unroll
    for (int r = 0; r < 32; r += 8) {
        float v = t[tx][ty + r];
        __nv_bfloat16 h, l;
        split2(v, h, l);
        size_t o = ((size_t)b * LSEQ + l0 + ty + r) * 512 + c0 + tx;
        XT_HI[o] = h;
        XT_LO[o] = l;
    }
}

// ---------------------------------------------------------------------------
// Stage q/k/v fp32 -> attention layouts (split bf16).
// z=0: q -> [bh][l][d] ; z=1: k -> [bh][l][d] ; z=2: v -> [bh][d][l]
// ---------------------------------------------------------------------------
__global__ void __launch_bounds__(256) stage_qkv_kernel()
{
    const int z  = blockIdx.z;
    const int bh = blockIdx.y;
    const int l0 = blockIdx.x * 64;
    const int tid = threadIdx.x;
    const float* src = (z == 0) ? g_q : (z == 1) ? g_k : g_v;
    const size_t base = (size_t)bh * 64 * LSEQ;

    if (z < 2) {
        __shared__ float t[64][65];
        __nv_bfloat16* dh = (z == 0) ? QT_HI : KT_HI;
        __nv_bfloat16* dl = (z == 0) ? QT_LO : KT_LO;
        int d  = tid >> 2;
        int ls = (tid & 3) * 16;
#pragma unroll
        for (int q = 0; q < 4; q++) {
            float4 v = *(const float4*)&src[base + (size_t)d * LSEQ + l0 + ls + q * 4];
            t[d][ls + q * 4 + 0] = v.x;
            t[d][ls + q * 4 + 1] = v.y;
            t[d][ls + q * 4 + 2] = v.z;
            t[d][ls + q * 4 + 3] = v.w;
        }
        __syncthreads();
        int l  = tid >> 2;
        int ds = (tid & 3) * 16;
        uint32_t hw[8], lw[8];
#pragma unroll
        for (int m = 0; m < 8; m++) {
            float f0 = t[ds + 2 * m][l];
            float f1 = t[ds + 2 * m + 1][l];
            split_pack(f1, f0, hw[m], lw[m]);
        }
        size_t wo = ((size_t)bh * LSEQ + l0 + l) * 32 + ds / 2;   // word offset
        *(uint4*)((uint32_t*)dh + wo)     = *(uint4*)&hw[0];
        *(uint4*)((uint32_t*)dh + wo + 4) = *(uint4*)&hw[4];
        *(uint4*)((uint32_t*)dl + wo)     = *(uint4*)&lw[0];
        *(uint4*)((uint32_t*)dl + wo + 4) = *(uint4*)&lw[4];
    } else {
        int d  = tid >> 2;
        int ls = (tid & 3) * 16;
        uint32_t hw[8], lw[8];
#pragma unroll
        for (int q = 0; q < 4; q++) {
            float4 v = *(const float4*)&src[base + (size_t)d * LSEQ + l0 + ls + q * 4];
            split_pack(v.y, v.x, hw[q * 2],     lw[q * 2]);
            split_pack(v.w, v.z, hw[q * 2 + 1], lw[q * 2 + 1]);
        }
        size_t wo = ((size_t)bh * 64 + d) * 1024 + (l0 + ls) / 2;
        *(uint4*)((uint32_t*)VT_HI + wo)     = *(uint4*)&hw[0];
        *(uint4*)((uint32_t*)VT_HI + wo + 4) = *(uint4*)&hw[4];
        *(uint4*)((uint32_t*)VT_LO + wo)     = *(uint4*)&lw[0];
        *(uint4*)((uint32_t*)VT_LO + wo + 4) = *(uint4*)&lw[4];
    }
}

// ---------------------------------------------------------------------------
// Conv via HMMA, split-bf16 3-term, cp.async double-buffered.
// Buffer layout (words): A_hi 0..2560, A_lo 2560..5120, B_hi 5120..6400,
// B_lo 6400..7680. Two buffers, stride 7680 words. Dyn smem 61440 B.
// ---------------------------------------------------------------------------
__device__ __forceinline__ void conv_fill(
    uint32_t smb, int bb, int ch, int co0, int l0, int b, int tid,
    const __nv_bfloat16* whi, const __nv_bfloat16* wlo)
{
    const int kk  = ch >> 4;
    const int ci0 = (ch & 15) << 5;
    const uint32_t bw = smb + bb * 7680 * 4;
    // A: 128 rows x 64B, 2 granules per thread (hi + lo)
    {
        int co = tid >> 1, seg = tid & 1;
        const char* sh = (const char*)whi +
            ((size_t)(co0 + co) * 1536 + kk * 512 + ci0 + seg * 16) * 2;
        const char* sl = (const char*)wlo +
            ((size_t)(co0 + co) * 1536 + kk * 512 + ci0 + seg * 16) * 2;
        uint32_t d0 = bw + (co * 20 + seg * 8) * 4;
        CPA(d0, sh);          CPA(d0 + 16, sh + 16);
        CPA(d0 + 10240, sl);  CPA(d0 + 10240 + 16, sl + 16);
    }
    // B: 64 rows x 64B, 1 granule per thread (hi + lo), zero-fill halo
    {
        int l = tid >> 2, seg = tid & 3;
        int gl = l0 + l + kk - 1;
        uint32_t ok = (gl >= 0 && gl < LSEQ) ? 16u : 0u;
        int glc = gl < 0 ? 0 : (gl > LSEQ - 1 ? LSEQ - 1 : gl);
        size_t so = ((size_t)b * LSEQ + glc) * 512 + ci0 + seg * 8;
        uint32_t d0 = bw + (5120 + l * 20 + seg * 4) * 4;
        CPA_Z(d0, (const char*)XT_HI + so * 2, ok);
        CPA_Z(d0 + 5120, (const char*)XT_LO + so * 2, ok);
    }
}

__global__ void __launch_bounds__(256) conv_qkv_mma(
    const float* __restrict__ bb0, const float* __restrict__ bb1,
    const float* __restrict__ bb2)
{
    extern __shared__ uint32_t cbuf[];
    const uint32_t smb = smem_u32(cbuf);

    const int c = blockIdx.z % 3;
    const int b = blockIdx.z / 3;
    const float* bias = (c == 0) ? bb0 : (c == 1) ? bb1 : bb2;
    float* y          = (c == 0) ? g_q : (c == 1) ? g_k : g_v;
    const __nv_bfloat16* whi = W_HI + (size_t)c * 786432;
    const __nv_bfloat16* wlo = W_LO + (size_t)c * 786432;

    const int co0 = blockIdx.y * 128;
    const int l0  = blockIdx.x * 64;
    const int tid = threadIdx.x;
    const int wid = tid >> 5, lane = tid & 31;
    const int wm = wid >> 2, wn = wid & 3;
    const int g = lane >> 2, t4 = lane & 3;

    float acc[4][2][4];
#pragma unroll
    for (int mt = 0; mt < 4; mt++)
#pragma unroll
        for (int nt = 0; nt < 2; nt++)
#pragma unroll
            for (int q = 0; q < 4; q++) acc[mt][nt][q] = 0.f;

    conv_fill(smb, 0, 0, co0, l0, b, tid, whi, wlo);
    CPC();

    for (int ch = 0; ch < 48; ch++) {
        CPW0();
        __syncthreads();
        if (ch + 1 < 48) {
            conv_fill(smb, (ch + 1) & 1, ch + 1, co0, l0, b, tid, whi, wlo);
            CPC();
        }
        const uint32_t* ash = cbuf + (ch & 1) * 7680;
        const uint32_t* bsh = ash + 5120;

#pragma unroll
        for (int ks = 0; ks < 2; ks++) {
            uint32_t Ah[4][4], Al[4][4], Bh[2][2], Bl[2][2];
#pragma unroll
            for (int mt = 0; mt < 4; mt++) {
                int r0 = (wm * 64 + mt * 16 + g) * 20 + ks * 8 + t4;
                int r1 = r0 + 160;
                Ah[mt][0] = ash[r0];     Ah[mt][1] = ash[r1];
                Ah[mt][2] = ash[r0 + 4]; Ah[mt][3] = ash[r1 + 4];
                Al[mt][0] = ash[2560 + r0];     Al[mt][1] = ash[2560 + r1];
                Al[mt][2] = ash[2560 + r0 + 4]; Al[mt][3] = ash[2560 + r1 + 4];
            }
#pragma unroll
            for (int nt = 0; nt < 2; nt++) {
                int c0w = (wn * 16 + nt * 8 + g) * 20 + ks * 8 + t4;
                Bh[nt][0] = bsh[c0w]; Bh[nt][1] = bsh[c0w + 4];
                Bl[nt][0] = bsh[1280 + c0w]; Bl[nt][1] = bsh[1280 + c0w + 4];
            }
#pragma unroll
            for (int mt = 0; mt < 4; mt++)
#pragma unroll
                for (int nt = 0; nt < 2; nt++) {
                    mma_bf16(acc[mt][nt], Ah[mt], Bh[nt]);
                    mma_bf16(acc[mt][nt], Ah[mt], Bl[nt]);
                    mma_bf16(acc[mt][nt], Al[mt], Bh[nt]);
                }
        }
    }

#pragma unroll
    for (int mt = 0; mt < 4; mt++) {
        int co = co0 + wm * 64 + mt * 16 + g;
        float bv0 = bias[co], bv1 = bias[co + 8];
#pragma unroll
        for (int nt = 0; nt < 2; nt++) {
            int lc = l0 + wn * 16 + nt * 8 + t4 * 2;
            size_t o0 = ((size_t)b * 512 + co) * LSEQ + lc;
            float2 v0 = make_float2(acc[mt][nt][0] + bv0, acc[mt][nt][1] + bv0);
            float2 v1 = make_float2(acc[mt][nt][2] + bv1, acc[mt][nt][3] + bv1);
            *(float2*)&y[o0]            = v0;
            *(float2*)&y[o0 + 8 * LSEQ] = v1;
        }
    }
}

// ---------------------------------------------------------------------------
// Flash attention on HMMA, pre-staged split-bf16, cp.async double-buffered.
// smem (110592 B): qsh 0..18432, qsl ..36864;
// buffers at 36864 + bb*36864: ksh(9216) ksl vsh vsl.
// Epilogue osf [64][132] f32 aliases buffer 0.
// ---------------------------------------------------------------------------
#define PW 36   // row pitch in words (72 bf16)

__device__ __forceinline__ void attn_fill_kv(uint32_t smb, int bb, int m0,
                                             int bh, int tid)
{
    const uint32_t bw = smb + 36864 + bb * 36864;
    int r  = tid >> 2;              // j for K, d for V
    int s2 = (tid & 3) * 2;         // first of 2 granules
    // K [bh][m0+j][d]
    {
        const char* sh = (const char*)KT_HI +
            (((size_t)bh * LSEQ + m0 + r) * 64 + s2 * 8) * 2;
        const char* sl = (const char*)KT_LO +
            (((size_t)bh * LSEQ + m0 + r) * 64 + s2 * 8) * 2;
        uint32_t d0 = bw + (r * PW + s2 * 4) * 4;
        CPA(d0, sh);         CPA(d0 + 16, sh + 16);
        CPA(d0 + 9216, sl);  CPA(d0 + 9216 + 16, sl + 16);
    }
    // V [bh][d][m0+j]
    {
        const char* sh = (const char*)VT_HI +
            (((size_t)bh * 64 + r) * LSEQ + m0 + s2 * 8) * 2;
        const char* sl = (const char*)VT_LO +
            (((size_t)bh * 64 + r) * LSEQ + m0 + s2 * 8) * 2;
        uint32_t d0 = bw + 18432 + (r * PW + s2 * 4) * 4;
        CPA(d0, sh);         CPA(d0 + 16, sh + 16);
        CPA(d0 + 9216, sl);  CPA(d0 + 9216 + 16, sl + 16);
    }
}

__global__ void __launch_bounds__(256) attn_tc(float* __restrict__ out)
{
    extern __shared__ char smc[];
    const uint32_t smb = smem_u32(smc);
    uint32_t* qsh = (uint32_t*)smc;
    uint32_t* qsl = qsh + 4608;
    float*    osf = (float*)(smc + 36864);

    const int bh  = blockIdx.y;
    const int i0  = blockIdx.x * 128;
    const int tid = threadIdx.x;
    const int w   = tid >> 5;
    const int lane = tid & 31;
    const int g = lane >> 2, t4 = lane & 3;
    const size_t base = (size_t)bh * 64 * LSEQ;

    // Q fill: 128 rows x 128B, 4 granules per thread (hi + lo)
    {
        int i  = tid >> 1;
        int s4 = (tid & 1) * 4;
        const char* sh = (const char*)QT_HI +
            (((size_t)bh * LSEQ + i0 + i) * 64 + s4 * 8) * 2;
        const char* sl = (const char*)QT_LO +
            (((size_t)bh * LSEQ + i0 + i) * 64 + s4 * 8) * 2;
        uint32_t d0 = smb + (i * PW + s4 * 4) * 4;
#pragma unroll
        for (int q = 0; q < 4; q++) {
            CPA(d0 + q * 16, sh + q * 16);
            CPA(d0 + 18432 + q * 16, sl + q * 16);
        }
    }
    attn_fill_kv(smb, 0, 0, bh, tid);
    CPC();

    float oacc[8][4];
#pragma unroll
    for (int nt = 0; nt < 8; nt++)
#pragma unroll
        for (int q = 0; q < 4; q++) oacc[nt][q] = 0.f;
    float m0r = -1e30f, m1r = -1e30f, l0r = 0.f, l1r = 0.f;

    for (int it = 0; it < 32; it++) {
        CPW0();
        __syncthreads();
        if (it + 1 < 32) {
            attn_fill_kv(smb, (it + 1) & 1, (it + 1) * 64, bh, tid);
            CPC();
        }
        const uint32_t* ksh = (uint32_t*)smc + 9216 + (it & 1) * 9216;
        const uint32_t* ksl = ksh + 2304;
        const uint32_t* vsh = ksh + 4608;
        const uint32_t* vsl = ksh + 6912;

        // ---- S = Q^T K (3-term split)
        float sa[8][4];
#pragma unroll
        for (int nt = 0; nt < 8; nt++)
#pragma unroll
            for (int q = 0; q < 4; q++) sa[nt][q] = 0.f;

#pragma unroll
        for (int ks = 0; ks < 4; ks++) {
            uint32_t ah[4], al[4];
            int ra = (w * 16 + g) * PW + ks * 8 + t4;
            ah[0] = qsh[ra]; ah[1] = qsh[ra + 8 * PW];
            ah[2] = qsh[ra + 4]; ah[3] = qsh[ra + 8 * PW + 4];
            al[0] = qsl[ra]; al[1] = qsl[ra + 8 * PW];
            al[2] = qsl[ra + 4]; al[3] = qsl[ra + 8 * PW + 4];
#pragma unroll
            for (int jt = 0; jt < 8; jt++) {
                uint32_t bhh[2], bll[2];
                int rb = (jt * 8 + g) * PW + ks * 8 + t4;
                bhh[0] = ksh[rb]; bhh[1] = ksh[rb + 4];
                bll[0] = ksl[rb]; bll[1] = ksl[rb + 4];
                mma_bf16(sa[jt], ah, bhh);
                mma_bf16(sa[jt], ah, bll);
                mma_bf16(sa[jt], al, bhh);
            }
        }

        // ---- online softmax (rows g, g+8)
        float mn0 = -1e30f, mn1 = -1e30f;
#pragma unroll
        for (int nt = 0; nt < 8; nt++) {
#pragma unroll
            for (int q = 0; q < 4; q++) sa[nt][q] *= ATT_SCALE;
            mn0 = fmaxf(mn0, fmaxf(sa[nt][0], sa[nt][1]));
            mn1 = fmaxf(mn1, fmaxf(sa[nt][2], sa[nt][3]));
        }
        mn0 = fmaxf(mn0, __shfl_xor_sync(0xffffffffu, mn0, 1));
        mn0 = fmaxf(mn0, __shfl_xor_sync(0xffffffffu, mn0, 2));
        mn1 = fmaxf(mn1, __shfl_xor_sync(0xffffffffu, mn1, 1));
        mn1 = fmaxf(mn1, __shfl_xor_sync(0xffffffffu, mn1, 2));

        float mnew0 = fmaxf(m0r, mn0), mnew1 = fmaxf(m1r, mn1);
        float alpha0 = __expf(m0r - mnew0), alpha1 = __expf(m1r - mnew1);
        m0r = mnew0; m1r = mnew1;

        float rs0 = 0.f, rs1 = 0.f;
#pragma unroll
        for (int nt = 0; nt < 8; nt++) {
            sa[nt][0] = __expf(sa[nt][0] - mnew0);
            sa[nt][1] = __expf(sa[nt][1] - mnew0);
            sa[nt][2] = __expf(sa[nt][2] - mnew1);
            sa[nt][3] = __expf(sa[nt][3] - mnew1);
            rs0 += sa[nt][0] + sa[nt][1];
            rs1 += sa[nt][2] + sa[nt][3];
        }
        rs0 += __shfl_xor_sync(0xffffffffu, rs0, 1);
        rs0 += __shfl_xor_sync(0xffffffffu, rs0, 2);
        rs1 += __shfl_xor_sync(0xffffffffu, rs1, 1);
        rs1 += __shfl_xor_sync(0xffffffffu, rs1, 2);
        l0r = l0r * alpha0 + rs0;
        l1r = l1r * alpha1 + rs1;

#pragma unroll
        for (int nt = 0; nt < 8; nt++) {
            oacc[nt][0] *= alpha0; oacc[nt][1] *= alpha0;
            oacc[nt][2] *= alpha1; oacc[nt][3] *= alpha1;
        }

        // ---- O += P V (P from registers)
#pragma unroll
        for (int ks = 0; ks < 4; ks++) {
            uint32_t ph[4], pl[4];
            split_pack(sa[2 * ks][1],     sa[2 * ks][0],     ph[0], pl[0]);
            split_pack(sa[2 * ks][3],     sa[2 * ks][2],     ph[1], pl[1]);
            split_pack(sa[2 * ks + 1][1], sa[2 * ks + 1][0], ph[2], pl[2]);
            split_pack(sa[2 * ks + 1][3], sa[2 * ks + 1][2], ph[3], pl[3]);
#pragma unroll
            for (int nt = 0; nt < 8; nt++) {
                uint32_t bhh[2], bll[2];
                int rb = (nt * 8 + g) * PW + ks * 8 + t4;
                bhh[0] = vsh[rb]; bhh[1] = vsh[rb + 4];
                bll[0] = vsl[rb]; bll[1] = vsl[rb + 4];
                mma_bf16(oacc[nt], ph, bhh);
                mma_bf16(oacc[nt], ph, bll);
                mma_bf16(oacc[nt], pl, bhh);
            }
        }
    }

    // ---- epilogue: normalize + transpose via smem (aliases buffer 0)
    {
        float inv0 = 1.f / l0r, inv1 = 1.f / l1r;
        int ir0 = w * 16 + g, ir1 = ir0 + 8;
#pragma unroll
        for (int nt = 0; nt < 8; nt++) {
            int d = nt * 8 + 2 * t4;
            osf[d * 132 + ir0]       = oacc[nt][0] * inv0;
            osf[(d + 1) * 132 + ir0] = oacc[nt][1] * inv0;
            osf[d * 132 + ir1]       = oacc[nt][2] * inv1;
            osf[(d + 1) * 132 + ir1] = oacc[nt][3] * inv1;
        }
    }
    __syncthreads();
#pragma unroll
    for (int r = 0; r < 8; r++) {
        int f4 = tid + r * 256;
        int d = f4 >> 5, ig = f4 & 31;
        float4 v = *(const float4*)&osf[d * 132 + ig * 4];
        *(float4*)&out[base + (size_t)d * LSEQ + i0 + ig * 4] = v;
    }
}

// ---------------------------------------------------------------------------
extern "C" void kernel_launch(void* const* d_in, const int* in_sizes, int n_in,
                              void* d_out, int out_size)
{
    const float* x  = (const float*)d_in[0];
    const float* w0 = (const float*)d_in[1];
    const float* b0 = (const float*)d_in[2];
    const float* w1 = (const float*)d_in[3];
    const float* b1 = (const float*)d_in[4];
    const float* w2 = (const float*)d_in[5];
    const float* b2 = (const float*)d_in[6];
    float* out = (float*)d_out;

    // 1) conv operand staging
    dim3 wgrid(786432 / 256, 3);
    split_w_kernel<<<wgrid, 256>>>(w0, w1, w2);
    dim3 xgrid(LSEQ / 32, 16, BATCH);
    split_x_kernel<<<xgrid, 256>>>(x);

    // 2) conv projections (cp.async pipelined)
    const int CSMEM = 61440;
    cudaFuncSetAttribute(conv_qkv_mma,
                         cudaFuncAttributeMaxDynamicSharedMemorySize, CSMEM);
    dim3 cgrid(LSEQ / 64, 4, 24);
    conv_qkv_mma<<<cgrid, 256, CSMEM>>>(b0, b1, b2);

    // 3) attention operand staging
    dim3 sgrid(LSEQ / 64, 64, 3);
    stage_qkv_kernel<<<sgrid, 256>>>();

    // 4) attention (cp.async pipelined)
    const int ASMEM = 110592;
    cudaFuncSetAttribute(attn_tc,
                         cudaFuncAttributeMaxDynamicSharedMemorySize, ASMEM);
    dim3 agrid(16, 64);
    attn_tc<<<agrid, 256, ASMEM>>>(out);
}

// round 13
// speedup vs baseline: 1.4894x; 1.4894x over previous
#include <cuda_runtime.h>
#include <cuda_bf16.h>
#include <cstdint>

#define LSEQ 2048
#define BATCH 8
// 1/sqrt(512)
#define ATT_SCALE 0.044194173824159216f

// fp32 conv outputs
__device__ float g_q[BATCH * 512 * LSEQ];
__device__ float g_k[BATCH * 512 * LSEQ];
__device__ float g_v[BATCH * 512 * LSEQ];
// conv operand staging (split bf16)
__device__ uint4 g_w_hi4[3 * 512 * 1536 / 8];      // [conv][co][k][ci]
__device__ uint4 g_w_lo4[3 * 512 * 1536 / 8];
__device__ uint4 g_xt_hi4[BATCH * LSEQ * 512 / 8]; // [b][l][ci]
__device__ uint4 g_xt_lo4[BATCH * LSEQ * 512 / 8];
// attention operand staging (split bf16)
__device__ uint4 g_qt_hi4[64 * LSEQ * 64 / 8];     // [bh][l][d]
__device__ uint4 g_qt_lo4[64 * LSEQ * 64 / 8];
__device__ uint4 g_kt_hi4[64 * LSEQ * 64 / 8];     // [bh][l][d]
__device__ uint4 g_kt_lo4[64 * LSEQ * 64 / 8];
__device__ uint4 g_vt_hi4[64 * 64 * LSEQ / 8];     // [bh][d][l]
__device__ uint4 g_vt_lo4[64 * 64 * LSEQ / 8];
#define W_HI ((__nv_bfloat16*)g_w_hi4)
#define W_LO ((__nv_bfloat16*)g_w_lo4)
#define XT_HI ((__nv_bfloat16*)g_xt_hi4)
#define XT_LO ((__nv_bfloat16*)g_xt_lo4)
#define QT_HI ((__nv_bfloat16*)g_qt_hi4)
#define QT_LO ((__nv_bfloat16*)g_qt_lo4)
#define KT_HI ((__nv_bfloat16*)g_kt_hi4)
#define KT_LO ((__nv_bfloat16*)g_kt_lo4)
#define VT_HI ((__nv_bfloat16*)g_vt_hi4)
#define VT_LO ((__nv_bfloat16*)g_vt_lo4)

__device__ __forceinline__ void split2(float f, __nv_bfloat16& h, __nv_bfloat16& l) {
    h = __float2bfloat16_rn(f);
    l = __float2bfloat16_rn(f - __bfloat162float(h));
}
__device__ __forceinline__ uint32_t cvt_bf16x2(float f1, float f0) {
    uint32_t r;
    asm("cvt.rn.bf16x2.f32 %0, %1, %2;" : "=r"(r) : "f"(f1), "f"(f0));
    return r;
}
__device__ __forceinline__ void split_pack(float f1, float f0,
                                           uint32_t& h, uint32_t& l) {
    h = cvt_bf16x2(f1, f0);
    float h0 = __uint_as_float(h << 16);
    float h1 = __uint_as_float(h & 0xffff0000u);
    l = cvt_bf16x2(f1 - h1, f0 - h0);
}
__device__ __forceinline__ void mma_bf16(float acc[4], const uint32_t a[4],
                                         const uint32_t b[2])
{
    asm volatile(
        "mma.sync.aligned.m16n8k16.row.col.f32.bf16.bf16.f32 "
        "{%0,%1,%2,%3}, {%4,%5,%6,%7}, {%8,%9}, {%0,%1,%2,%3};\n"
        : "+f"(acc[0]), "+f"(acc[1]), "+f"(acc[2]), "+f"(acc[3])
        : "r"(a[0]), "r"(a[1]), "r"(a[2]), "r"(a[3]), "r"(b[0]), "r"(b[1]));
}

// ---------------------------------------------------------------------------
// w[co][ci][k] fp32 -> w_hi/lo[conv][co][k][ci] bf16
// ---------------------------------------------------------------------------
__global__ void __launch_bounds__(256) split_w_kernel(
    const float* __restrict__ w0, const float* __restrict__ w1,
    const float* __restrict__ w2)
{
    const int conv = blockIdx.y;
    const float* w = (conv == 0) ? w0 : (conv == 1) ? w1 : w2;
    int idx = blockIdx.x * 256 + threadIdx.x;
    int co = idx / 1536, r = idx - co * 1536;
    int kk = r >> 9, ci = r & 511;
    float f = w[(size_t)co * 1536 + ci * 3 + kk];
    __nv_bfloat16 h, l;
    split2(f, h, l);
    size_t o = (size_t)conv * 786432 + idx;
    W_HI[o] = h;
    W_LO[o] = l;
}

// ---------------------------------------------------------------------------
// x[b][ci][l] fp32 -> xt_hi/lo[b][l][ci] bf16, 32x32 smem transpose
// ---------------------------------------------------------------------------
__global__ void __launch_bounds__(256) split_x_kernel(const float* __restrict__ x)
{
    __shared__ float t[32][33];
    const int b = blockIdx.z, c0 = blockIdx.y * 32, l0 = blockIdx.x * 32;
    const int tx = threadIdx.x & 31, ty = threadIdx.x >> 5;
#pragma unroll
    for (int r = 0; r < 32; r += 8)
        t[ty + r][tx] = x[((size_t)b * 512 + c0 + ty + r) * LSEQ + l0 + tx];
    __syncthreads();
#pragma unroll
    for (int r = 0; r < 32; r += 8) {
        float v = t[tx][ty + r];
        __nv_bfloat16 h, l;
        split2(v, h, l);
        size_t o = ((size_t)b * LSEQ + l0 + ty + r) * 512 + c0 + tx;
        XT_HI[o] = h;
        XT_LO[o] = l;
    }
}

// ---------------------------------------------------------------------------
// Stage q/k/v fp32 -> attention layouts (split bf16), proven R12.
// z=0: q -> [bh][l][d] ; z=1: k -> [bh][l][d] ; z=2: v -> [bh][d][l]
// ---------------------------------------------------------------------------
__global__ void __launch_bounds__(256) stage_qkv_kernel()
{
    const int z  = blockIdx.z;
    const int bh = blockIdx.y;
    const int l0 = blockIdx.x * 64;
    const int tid = threadIdx.x;
    const float* src = (z == 0) ? g_q : (z == 1) ? g_k : g_v;
    const size_t base = (size_t)bh * 64 * LSEQ;

    if (z < 2) {
        __shared__ float t[64][65];
        __nv_bfloat16* dh = (z == 0) ? QT_HI : KT_HI;
        __nv_bfloat16* dl = (z == 0) ? QT_LO : KT_LO;
        int d  = tid >> 2;
        int ls = (tid & 3) * 16;
#pragma unroll
        for (int q = 0; q < 4; q++) {
            float4 v = *(const float4*)&src[base + (size_t)d * LSEQ + l0 + ls + q * 4];
            t[d][ls + q * 4 + 0] = v.x;
            t[d][ls + q * 4 + 1] = v.y;
            t[d][ls + q * 4 + 2] = v.z;
            t[d][ls + q * 4 + 3] = v.w;
        }
        __syncthreads();
        int l  = tid >> 2;
        int ds = (tid & 3) * 16;
        uint32_t hw[8], lw[8];
#pragma unroll
        for (int m = 0; m < 8; m++) {
            float f0 = t[ds + 2 * m][l];
            float f1 = t[ds + 2 * m + 1][l];
            split_pack(f1, f0, hw[m], lw[m]);
        }
        size_t wo = ((size_t)bh * LSEQ + l0 + l) * 32 + ds / 2;
        *(uint4*)((uint32_t*)dh + wo)     = *(uint4*)&hw[0];
        *(uint4*)((uint32_t*)dh + wo + 4) = *(uint4*)&hw[4];
        *(uint4*)((uint32_t*)dl + wo)     = *(uint4*)&lw[0];
        *(uint4*)((uint32_t*)dl + wo + 4) = *(uint4*)&lw[4];
    } else {
        int d  = tid >> 2;
        int ls = (tid & 3) * 16;
        uint32_t hw[8], lw[8];
#pragma unroll
        for (int q = 0; q < 4; q++) {
            float4 v = *(const float4*)&src[base + (size_t)d * LSEQ + l0 + ls + q * 4];
            split_pack(v.y, v.x, hw[q * 2],     lw[q * 2]);
            split_pack(v.w, v.z, hw[q * 2 + 1], lw[q * 2 + 1]);
        }
        size_t wo = ((size_t)bh * 64 + d) * 1024 + (l0 + ls) / 2;
        *(uint4*)((uint32_t*)VT_HI + wo)     = *(uint4*)&hw[0];
        *(uint4*)((uint32_t*)VT_HI + wo + 4) = *(uint4*)&hw[4];
        *(uint4*)((uint32_t*)VT_LO + wo)     = *(uint4*)&lw[0];
        *(uint4*)((uint32_t*)VT_LO + wo + 4) = *(uint4*)&lw[4];
    }
}

// ---------------------------------------------------------------------------
// Conv via HMMA, split-bf16 3-term — R9 version verbatim (proven).
// ---------------------------------------------------------------------------
__global__ void __launch_bounds__(256) conv_qkv_mma(
    const float* __restrict__ bb0, const float* __restrict__ bb1,
    const float* __restrict__ bb2)
{
    __shared__ uint32_t ash[2560 * 2];
    __shared__ uint32_t bsh[1280 * 2];

    const int c = blockIdx.z % 3;
    const int b = blockIdx.z / 3;
    const float* bias = (c == 0) ? bb0 : (c == 1) ? bb1 : bb2;
    float* y          = (c == 0) ? g_q : (c == 1) ? g_k : g_v;
    const __nv_bfloat16* whi = W_HI + (size_t)c * 786432;
    const __nv_bfloat16* wlo = W_LO + (size_t)c * 786432;

    const int co0 = blockIdx.y * 128;
    const int l0  = blockIdx.x * 64;
    const int tid = threadIdx.x;
    const int wid = tid >> 5, lane = tid & 31;
    const int wm = wid >> 2, wn = wid & 3;
    const int g = lane >> 2, t4 = lane & 3;

    float acc[4][2][4];
#pragma unroll
    for (int mt = 0; mt < 4; mt++)
#pragma unroll
        for (int nt = 0; nt < 2; nt++)
#pragma unroll
            for (int q = 0; q < 4; q++) acc[mt][nt][q] = 0.f;

    const int a_co = tid >> 1;
    const int b_l  = tid >> 2;
    const int b_sg = (tid & 3) * 8;

    for (int ch = 0; ch < 48; ch++) {
        const int kk  = ch >> 4;
        const int ci0 = (ch & 15) << 5;
        __syncthreads();
        {
            size_t base = (size_t)(co0 + a_co) * 1536 + kk * 512 + ci0;
#pragma unroll
            for (int it = 0; it < 2; it++) {
                int seg = ((tid & 1) + 2 * it) * 8;
                uint4 vh = *(const uint4*)(whi + base + seg);
                uint4 vl = *(const uint4*)(wlo + base + seg);
                *(uint4*)&ash[a_co * 20 + seg / 2]        = vh;
                *(uint4*)&ash[2560 + a_co * 20 + seg / 2] = vl;
            }
        }
        {
            int gl = l0 + b_l + kk - 1;
            uint4 vh = make_uint4(0, 0, 0, 0), vl = make_uint4(0, 0, 0, 0);
            if (gl >= 0 && gl < LSEQ) {
                size_t base = ((size_t)b * LSEQ + gl) * 512 + ci0 + b_sg;
                vh = *(const uint4*)(XT_HI + base);
                vl = *(const uint4*)(XT_LO + base);
            }
            *(uint4*)&bsh[b_l * 20 + b_sg / 2]        = vh;
            *(uint4*)&bsh[1280 + b_l * 20 + b_sg / 2] = vl;
        }
        __syncthreads();

#pragma unroll
        for (int ks = 0; ks < 2; ks++) {
            uint32_t Ah[4][4], Al[4][4], Bh[2][2], Bl[2][2];
#pragma unroll
            for (int mt = 0; mt < 4; mt++) {
                int r0 = (wm * 64 + mt * 16 + g) * 20 + ks * 8 + t4;
                int r1 = r0 + 160;
                Ah[mt][0] = ash[r0];     Ah[mt][1] = ash[r1];
                Ah[mt][2] = ash[r0 + 4]; Ah[mt][3] = ash[r1 + 4];
                Al[mt][0] = ash[2560 + r0];     Al[mt][1] = ash[2560 + r1];
                Al[mt][2] = ash[2560 + r0 + 4]; Al[mt][3] = ash[2560 + r1 + 4];
            }
#pragma unroll
            for (int nt = 0; nt < 2; nt++) {
                int c0w = (wn * 16 + nt * 8 + g) * 20 + ks * 8 + t4;
                Bh[nt][0] = bsh[c0w]; Bh[nt][1] = bsh[c0w + 4];
                Bl[nt][0] = bsh[1280 + c0w]; Bl[nt][1] = bsh[1280 + c0w + 4];
            }
#pragma unroll
            for (int mt = 0; mt < 4; mt++)
#pragma unroll
                for (int nt = 0; nt < 2; nt++) {
                    mma_bf16(acc[mt][nt], Ah[mt], Bh[nt]);
                    mma_bf16(acc[mt][nt], Ah[mt], Bl[nt]);
                    mma_bf16(acc[mt][nt], Al[mt], Bh[nt]);
                }
        }
    }

#pragma unroll
    for (int mt = 0; mt < 4; mt++) {
        int co = co0 + wm * 64 + mt * 16 + g;
        float bv0 = bias[co], bv1 = bias[co + 8];
#pragma unroll
        for (int nt = 0; nt < 2; nt++) {
            int lc = l0 + wn * 16 + nt * 8 + t4 * 2;
            size_t o0 = ((size_t)b * 512 + co) * LSEQ + lc;
            float2 v0 = make_float2(acc[mt][nt][0] + bv0, acc[mt][nt][1] + bv0);
            float2 v1 = make_float2(acc[mt][nt][2] + bv1, acc[mt][nt][3] + bv1);
            *(float2*)&y[o0]            = v0;
            *(float2*)&y[o0 + 8 * LSEQ] = v1;
        }
    }
}

// ---------------------------------------------------------------------------
// Flash attention on HMMA — R10 structure (proven 749us), ONE change:
// K/V tiles now copied from pre-staged split-bf16 gmem with LDG.128+STS.128
// (no in-loop conversion, no 2-byte scatter). Same smem layout/occupancy.
// ---------------------------------------------------------------------------
#define PW 36   // row pitch in words (72 bf16)

__global__ void __launch_bounds__(256, 2) attn_tc(float* __restrict__ out)
{
    extern __shared__ char smc[];
    uint32_t* qsh = (uint32_t*)(smc);
    uint32_t* qsl = (uint32_t*)(smc + 18432);
    uint32_t* ksh = (uint32_t*)(smc + 36864);
    uint32_t* ksl = (uint32_t*)(smc + 46080);
    uint32_t* vsh = (uint32_t*)(smc + 55296);
    uint32_t* vsl = (uint32_t*)(smc + 64512);
    float*    osf = (float*)(smc + 36864);   // epilogue alias

    const int bh  = blockIdx.y;
    const int i0  = blockIdx.x * 128;
    const int tid = threadIdx.x;
    const int w   = tid >> 5;
    const int lane = tid & 31;
    const int g   = lane >> 2, t4 = lane & 3;
    const size_t base = (size_t)bh * 64 * LSEQ;

    // ---- Q fill (once): [i][d] rows of 64 bf16 from QT_HI/LO [bh][l][d]
    {
        int i = tid >> 1;                    // 0..127
        int s = (tid & 1) * 4;               // uint4 granule base (of 8)
        const uint32_t* qh = (const uint32_t*)QT_HI +
            ((size_t)bh * LSEQ + i0 + i) * 32;
        const uint32_t* ql = (const uint32_t*)QT_LO +
            ((size_t)bh * LSEQ + i0 + i) * 32;
#pragma unroll
        for (int q = 0; q < 4; q++) {
            *(uint4*)&qsh[i * PW + (s + q) * 4] = *(const uint4*)(qh + (s + q) * 4);
            *(uint4*)&qsl[i * PW + (s + q) * 4] = *(const uint4*)(ql + (s + q) * 4);
        }
    }

    float oacc[8][4];
#pragma unroll
    for (int nt = 0; nt < 8; nt++)
#pragma unroll
        for (int q = 0; q < 4; q++) oacc[nt][q] = 0.f;
    float m0r = -1e30f, m1r = -1e30f, l0r = 0.f, l1r = 0.f;

    const int fr = tid >> 2;            // fill row (j for K, d for V)
    const int fc = (tid & 3) * 2;       // uint4 granule pair base

    for (int m0 = 0; m0 < LSEQ; m0 += 64) {
        __syncthreads();   // prev PV done before overwriting ks/vs
        // ---- K fill: ks[j][d] from KT [bh][m0+j][d]
        {
            const uint32_t* kh = (const uint32_t*)KT_HI +
                ((size_t)bh * LSEQ + m0 + fr) * 32;
            const uint32_t* kl = (const uint32_t*)KT_LO +
                ((size_t)bh * LSEQ + m0 + fr) * 32;
            *(uint4*)&ksh[fr * PW + fc * 4]       = *(const uint4*)(kh + fc * 4);
            *(uint4*)&ksh[fr * PW + (fc + 1) * 4] = *(const uint4*)(kh + (fc + 1) * 4);
            *(uint4*)&ksl[fr * PW + fc * 4]       = *(const uint4*)(kl + fc * 4);
            *(uint4*)&ksl[fr * PW + (fc + 1) * 4] = *(const uint4*)(kl + (fc + 1) * 4);
            // ---- V fill: vs[d][j] from VT [bh][d][m0+j]
            const uint32_t* vh = (const uint32_t*)VT_HI +
                ((size_t)bh * 64 + fr) * 1024 + m0 / 2;
            const uint32_t* vl = (const uint32_t*)VT_LO +
                ((size_t)bh * 64 + fr) * 1024 + m0 / 2;
            *(uint4*)&vsh[fr * PW + fc * 4]       = *(const uint4*)(vh + fc * 4);
            *(uint4*)&vsh[fr * PW + (fc + 1) * 4] = *(const uint4*)(vh + (fc + 1) * 4);
            *(uint4*)&vsl[fr * PW + fc * 4]       = *(const uint4*)(vl + fc * 4);
            *(uint4*)&vsl[fr * PW + (fc + 1) * 4] = *(const uint4*)(vl + (fc + 1) * 4);
        }
        __syncthreads();

        // ---- S = Q^T K (3-term split)
        float sa[8][4];
#pragma unroll
        for (int nt = 0; nt < 8; nt++)
#pragma unroll
            for (int q = 0; q < 4; q++) sa[nt][q] = 0.f;

#pragma unroll
        for (int ks = 0; ks < 4; ks++) {
            uint32_t ah[4], al[4];
            int ra = (w * 16 + g) * PW + ks * 8 + t4;
            ah[0] = qsh[ra]; ah[1] = qsh[ra + 8 * PW];
            ah[2] = qsh[ra + 4]; ah[3] = qsh[ra + 8 * PW + 4];
            al[0] = qsl[ra]; al[1] = qsl[ra + 8 * PW];
            al[2] = qsl[ra + 4]; al[3] = qsl[ra + 8 * PW + 4];
#pragma unroll
            for (int jt = 0; jt < 8; jt++) {
                uint32_t bhh[2], bll[2];
                int rb = (jt * 8 + g) * PW + ks * 8 + t4;
                bhh[0] = ksh[rb]; bhh[1] = ksh[rb + 4];
                bll[0] = ksl[rb]; bll[1] = ksl[rb + 4];
                mma_bf16(sa[jt], ah, bhh);
                mma_bf16(sa[jt], ah, bll);
                mma_bf16(sa[jt], al, bhh);
            }
        }

        // ---- online softmax (rows g, g+8)
        float mn0 = -1e30f, mn1 = -1e30f;
#pragma unroll
        for (int nt = 0; nt < 8; nt++) {
#pragma unroll
            for (int q = 0; q < 4; q++) sa[nt][q] *= ATT_SCALE;
            mn0 = fmaxf(mn0, fmaxf(sa[nt][0], sa[nt][1]));
            mn1 = fmaxf(mn1, fmaxf(sa[nt][2], sa[nt][3]));
        }
        mn0 = fmaxf(mn0, __shfl_xor_sync(0xffffffffu, mn0, 1));
        mn0 = fmaxf(mn0, __shfl_xor_sync(0xffffffffu, mn0, 2));
        mn1 = fmaxf(mn1, __shfl_xor_sync(0xffffffffu, mn1, 1));
        mn1 = fmaxf(mn1, __shfl_xor_sync(0xffffffffu, mn1, 2));

        float mnew0 = fmaxf(m0r, mn0), mnew1 = fmaxf(m1r, mn1);
        float alpha0 = __expf(m0r - mnew0), alpha1 = __expf(m1r - mnew1);
        m0r = mnew0; m1r = mnew1;

        float rs0 = 0.f, rs1 = 0.f;
#pragma unroll
        for (int nt = 0; nt < 8; nt++) {
            sa[nt][0] = __expf(sa[nt][0] - mnew0);
            sa[nt][1] = __expf(sa[nt][1] - mnew0);
            sa[nt][2] = __expf(sa[nt][2] - mnew1);
            sa[nt][3] = __expf(sa[nt][3] - mnew1);
            rs0 += sa[nt][0] + sa[nt][1];
            rs1 += sa[nt][2] + sa[nt][3];
        }
        rs0 += __shfl_xor_sync(0xffffffffu, rs0, 1);
        rs0 += __shfl_xor_sync(0xffffffffu, rs0, 2);
        rs1 += __shfl_xor_sync(0xffffffffu, rs1, 1);
        rs1 += __shfl_xor_sync(0xffffffffu, rs1, 2);
        l0r = l0r * alpha0 + rs0;
        l1r = l1r * alpha1 + rs1;

#pragma unroll
        for (int nt = 0; nt < 8; nt++) {
            oacc[nt][0] *= alpha0; oacc[nt][1] *= alpha0;
            oacc[nt][2] *= alpha1; oacc[nt][3] *= alpha1;
        }

        // ---- O += P V (P from registers)
#pragma unroll
        for (int ks = 0; ks < 4; ks++) {
            uint32_t ph[4], pl[4];
            split_pack(sa[2 * ks][1],     sa[2 * ks][0],     ph[0], pl[0]);
            split_pack(sa[2 * ks][3],     sa[2 * ks][2],     ph[1], pl[1]);
            split_pack(sa[2 * ks + 1][1], sa[2 * ks + 1][0], ph[2], pl[2]);
            split_pack(sa[2 * ks + 1][3], sa[2 * ks + 1][2], ph[3], pl[3]);
#pragma unroll
            for (int nt = 0; nt < 8; nt++) {
                uint32_t bhh[2], bll[2];
                int rb = (nt * 8 + g) * PW + ks * 8 + t4;
                bhh[0] = vsh[rb]; bhh[1] = vsh[rb + 4];
                bll[0] = vsl[rb]; bll[1] = vsl[rb + 4];
                mma_bf16(oacc[nt], ph, bhh);
                mma_bf16(oacc[nt], ph, bll);
                mma_bf16(oacc[nt], pl, bhh);
            }
        }
    }

    // ---- epilogue: normalize + transpose via smem
    __syncthreads();
    {
        float inv0 = 1.f / l0r, inv1 = 1.f / l1r;
        int ir0 = w * 16 + g, ir1 = ir0 + 8;
#pragma unroll
        for (int nt = 0; nt < 8; nt++) {
            int d = nt * 8 + 2 * t4;
            osf[d * 132 + ir0]       = oacc[nt][0] * inv0;
            osf[(d + 1) * 132 + ir0] = oacc[nt][1] * inv0;
            osf[d * 132 + ir1]       = oacc[nt][2] * inv1;
            osf[(d + 1) * 132 + ir1] = oacc[nt][3] * inv1;
        }
    }
    __syncthreads();
#pragma unroll
    for (int r = 0; r < 8; r++) {
        int f4 = tid + r * 256;
        int d = f4 >> 5, ig = f4 & 31;
        float4 v = *(const float4*)&osf[d * 132 + ig * 4];
        *(float4*)&out[base + (size_t)d * LSEQ + i0 + ig * 4] = v;
    }
}

// ---------------------------------------------------------------------------
extern "C" void kernel_launch(void* const* d_in, const int* in_sizes, int n_in,
                              void* d_out, int out_size)
{
    const float* x  = (const float*)d_in[0];
    const float* w0 = (const float*)d_in[1];
    const float* b0 = (const float*)d_in[2];
    const float* w1 = (const float*)d_in[3];
    const float* b1 = (const float*)d_in[4];
    const float* w2 = (const float*)d_in[5];
    const float* b2 = (const float*)d_in[6];
    float* out = (float*)d_out;

    // 1) conv operand staging
    dim3 wgrid(786432 / 256, 3);
    split_w_kernel<<<wgrid, 256>>>(w0, w1, w2);
    dim3 xgrid(LSEQ / 32, 16, BATCH);
    split_x_kernel<<<xgrid, 256>>>(x);

    // 2) conv projections (R9 proven)
    dim3 cgrid(LSEQ / 64, 4, 24);
    conv_qkv_mma<<<cgrid, 256>>>(b0, b1, b2);

    // 3) attention operand staging
    dim3 sgrid(LSEQ / 64, 64, 3);
    stage_qkv_kernel<<<sgrid, 256>>>();

    // 4) attention
    const int ASMEM = 73728;
    cudaFuncSetAttribute(attn_tc,
                         cudaFuncAttributeMaxDynamicSharedMemorySize, ASMEM);
    dim3 agrid(16, 64);
    attn_tc<<<agrid, 256, ASMEM>>>(out);
}

// round 14
// speedup vs baseline: 1.5671x; 1.0522x over previous
#include <cuda_runtime.h>
#include <cuda_bf16.h>
#include <cstdint>

#define LSEQ 2048
#define BATCH 8
// 1/sqrt(512)
#define ATT_SCALE 0.044194173824159216f

// fp32 conv outputs
__device__ float g_q[BATCH * 512 * LSEQ];
__device__ float g_k[BATCH * 512 * LSEQ];
__device__ float g_v[BATCH * 512 * LSEQ];
// conv operand staging (split bf16)
__device__ uint4 g_w_hi4[3 * 512 * 1536 / 8];      // [conv][co][k][ci]
__device__ uint4 g_w_lo4[3 * 512 * 1536 / 8];
__device__ uint4 g_xt_hi4[BATCH * LSEQ * 512 / 8]; // [b][l][ci]
__device__ uint4 g_xt_lo4[BATCH * LSEQ * 512 / 8];
// attention operand staging (split bf16)
__device__ uint4 g_qt_hi4[64 * LSEQ * 64 / 8];     // [bh][l][d]
__device__ uint4 g_qt_lo4[64 * LSEQ * 64 / 8];
__device__ uint4 g_kt_hi4[64 * LSEQ * 64 / 8];     // [bh][l][d]
__device__ uint4 g_kt_lo4[64 * LSEQ * 64 / 8];
__device__ uint4 g_vt_hi4[64 * 64 * LSEQ / 8];     // [bh][d][l]
__device__ uint4 g_vt_lo4[64 * 64 * LSEQ / 8];
#define W_HI ((__nv_bfloat16*)g_w_hi4)
#define W_LO ((__nv_bfloat16*)g_w_lo4)
#define XT_HI ((__nv_bfloat16*)g_xt_hi4)
#define XT_LO ((__nv_bfloat16*)g_xt_lo4)
#define QT_HI ((__nv_bfloat16*)g_qt_hi4)
#define QT_LO ((__nv_bfloat16*)g_qt_lo4)
#define KT_HI ((__nv_bfloat16*)g_kt_hi4)
#define KT_LO ((__nv_bfloat16*)g_kt_lo4)
#define VT_HI ((__nv_bfloat16*)g_vt_hi4)
#define VT_LO ((__nv_bfloat16*)g_vt_lo4)

__device__ __forceinline__ uint32_t smem_u32(const void* p) {
    uint32_t a;
    asm("{ .reg .u64 t; cvta.to.shared.u64 t, %1; cvt.u32.u64 %0, t; }"
        : "=r"(a) : "l"(p));
    return a;
}
#define CPA(dst, src) \
    asm volatile("cp.async.ca.shared.global [%0], [%1], 16;" \
                 :: "r"(dst), "l"(src))
#define CPA_Z(dst, src, sz) \
    asm volatile("cp.async.ca.shared.global [%0], [%1], 16, %2;" \
                 :: "r"(dst), "l"(src), "r"(sz))
#define CPC()  asm volatile("cp.async.commit_group;")
#define CPW0() asm volatile("cp.async.wait_group 0;")

__device__ __forceinline__ void split2(float f, __nv_bfloat16& h, __nv_bfloat16& l) {
    h = __float2bfloat16_rn(f);
    l = __float2bfloat16_rn(f - __bfloat162float(h));
}
__device__ __forceinline__ uint32_t cvt_bf16x2(float f1, float f0) {
    uint32_t r;
    asm("cvt.rn.bf16x2.f32 %0, %1, %2;" : "=r"(r) : "f"(f1), "f"(f0));
    return r;
}
__device__ __forceinline__ void split_pack(float f1, float f0,
                                           uint32_t& h, uint32_t& l) {
    h = cvt_bf16x2(f1, f0);
    float h0 = __uint_as_float(h << 16);
    float h1 = __uint_as_float(h & 0xffff0000u);
    l = cvt_bf16x2(f1 - h1, f0 - h0);
}
__device__ __forceinline__ void mma_bf16(float acc[4], const uint32_t a[4],
                                         const uint32_t b[2])
{
    asm volatile(
        "mma.sync.aligned.m16n8k16.row.col.f32.bf16.bf16.f32 "
        "{%0,%1,%2,%3}, {%4,%5,%6,%7}, {%8,%9}, {%0,%1,%2,%3};\n"
        : "+f"(acc[0]), "+f"(acc[1]), "+f"(acc[2]), "+f"(acc[3])
        : "r"(a[0]), "r"(a[1]), "r"(a[2]), "r"(a[3]), "r"(b[0]), "r"(b[1]));
}

// ---------------------------------------------------------------------------
// w[co][ci][k] fp32 -> w_hi/lo[conv][co][k][ci] bf16
// ---------------------------------------------------------------------------
__global__ void __launch_bounds__(256) split_w_kernel(
    const float* __restrict__ w0, const float* __restrict__ w1,
    const float* __restrict__ w2)
{
    const int conv = blockIdx.y;
    const float* w = (conv == 0) ? w0 : (conv == 1) ? w1 : w2;
    int idx = blockIdx.x * 256 + threadIdx.x;
    int co = idx / 1536, r = idx - co * 1536;
    int kk = r >> 9, ci = r & 511;
    float f = w[(size_t)co * 1536 + ci * 3 + kk];
    __nv_bfloat16 h, l;
    split2(f, h, l);
    size_t o = (size_t)conv * 786432 + idx;
    W_HI[o] = h;
    W_LO[o] = l;
}

// ---------------------------------------------------------------------------
// x[b][ci][l] fp32 -> xt_hi/lo[b][l][ci] bf16, 32x32 smem transpose
// ---------------------------------------------------------------------------
__global__ void __launch_bounds__(256) split_x_kernel(const float* __restrict__ x)
{
    __shared__ float t[32][33];
    const int b = blockIdx.z, c0 = blockIdx.y * 32, l0 = blockIdx.x * 32;
    const int tx = threadIdx.x & 31, ty = threadIdx.x >> 5;
#pragma unroll
    for (int r = 0; r < 32; r += 8)
        t[ty + r][tx] = x[((size_t)b * 512 + c0 + ty + r) * LSEQ + l0 + tx];
    __syncthreads();
#pragma unroll
    for (int r = 0; r < 32; r += 8) {
        float v = t[tx][ty + r];
        __nv_bfloat16 h, l;
        split2(v, h, l);
        size_t o = ((size_t)b * LSEQ + l0 + ty + r) * 512 + c0 + tx;
        XT_HI[o] = h;
        XT_LO[o] = l;
    }
}

// ---------------------------------------------------------------------------
// Stage q/k/v fp32 -> attention layouts (split bf16), proven.
// z=0: q -> [bh][l][d] ; z=1: k -> [bh][l][d] ; z=2: v -> [bh][d][l]
// ---------------------------------------------------------------------------
__global__ void __launch_bounds__(256) stage_qkv_kernel()
{
    const int z  = blockIdx.z;
    const int bh = blockIdx.y;
    const int l0 = blockIdx.x * 64;
    const int tid = threadIdx.x;
    const float* src = (z == 0) ? g_q : (z == 1) ? g_k : g_v;
    const size_t base = (size_t)bh * 64 * LSEQ;

    if (z < 2) {
        __shared__ float t[64][65];
        __nv_bfloat16* dh = (z == 0) ? QT_HI : KT_HI;
        __nv_bfloat16* dl = (z == 0) ? QT_LO : KT_LO;
        int d  = tid >> 2;
        int ls = (tid & 3) * 16;
#pragma unroll
        for (int q = 0; q < 4; q++) {
            float4 v = *(const float4*)&src[base + (size_t)d * LSEQ + l0 + ls + q * 4];
            t[d][ls + q * 4 + 0] = v.x;
            t[d][ls + q * 4 + 1] = v.y;
            t[d][ls + q * 4 + 2] = v.z;
            t[d][ls + q * 4 + 3] = v.w;
        }
        __syncthreads();
        int l  = tid >> 2;
        int ds = (tid & 3) * 16;
        uint32_t hw[8], lw[8];
#pragma unroll
        for (int m = 0; m < 8; m++) {
            float f0 = t[ds + 2 * m][l];
            float f1 = t[ds + 2 * m + 1][l];
            split_pack(f1, f0, hw[m], lw[m]);
        }
        size_t wo = ((size_t)bh * LSEQ + l0 + l) * 32 + ds / 2;
        *(uint4*)((uint32_t*)dh + wo)     = *(uint4*)&hw[0];
        *(uint4*)((uint32_t*)dh + wo + 4) = *(uint4*)&hw[4];
        *(uint4*)((uint32_t*)dl + wo)     = *(uint4*)&lw[0];
        *(uint4*)((uint32_t*)dl + wo + 4) = *(uint4*)&lw[4];
    } else {
        int d  = tid >> 2;
        int ls = (tid & 3) * 16;
        uint32_t hw[8], lw[8];
#pragma unroll
        for (int q = 0; q < 4; q++) {
            float4 v = *(const float4*)&src[base + (size_t)d * LSEQ + l0 + ls + q * 4];
            split_pack(v.y, v.x, hw[q * 2],     lw[q * 2]);
            split_pack(v.w, v.z, hw[q * 2 + 1], lw[q * 2 + 1]);
        }
        size_t wo = ((size_t)bh * 64 + d) * 1024 + (l0 + ls) / 2;
        *(uint4*)((uint32_t*)VT_HI + wo)     = *(uint4*)&hw[0];
        *(uint4*)((uint32_t*)VT_HI + wo + 4) = *(uint4*)&hw[4];
        *(uint4*)((uint32_t*)VT_LO + wo)     = *(uint4*)&lw[0];
        *(uint4*)((uint32_t*)VT_LO + wo + 4) = *(uint4*)&lw[4];
    }
}

// ---------------------------------------------------------------------------
// Conv via HMMA, split-bf16 3-term, cp.async double-buffered (isolated test).
// Buffer (words): A_hi 0..2560, A_lo ..5120, B_hi ..6400, B_lo ..7680.
// Two buffers, stride 7680 words, dyn smem 61440 B (3 CTAs/SM).
// ---------------------------------------------------------------------------
__device__ __forceinline__ void conv_fill(
    uint32_t smb, int bb, int ch, int co0, int l0, int b, int tid,
    const __nv_bfloat16* whi, const __nv_bfloat16* wlo)
{
    const int kk  = ch >> 4;
    const int ci0 = (ch & 15) << 5;
    const uint32_t bw = smb + bb * 7680 * 4;
    // A: 128 rows x 64B, 2 threads/row, 32B each (hi + lo)
    {
        int co = tid >> 1, seg = tid & 1;
        const char* sh = (const char*)whi +
            ((size_t)(co0 + co) * 1536 + kk * 512 + ci0 + seg * 16) * 2;
        const char* sl = (const char*)wlo +
            ((size_t)(co0 + co) * 1536 + kk * 512 + ci0 + seg * 16) * 2;
        uint32_t d0 = bw + (co * 20 + seg * 8) * 4;
        CPA(d0, sh);          CPA(d0 + 16, sh + 16);
        CPA(d0 + 10240, sl);  CPA(d0 + 10240 + 16, sl + 16);
    }
    // B: 64 rows x 64B, 4 threads/row, 16B each (hi + lo), zero-fill halo
    {
        int l = tid >> 2, seg = tid & 3;
        int gl = l0 + l + kk - 1;
        uint32_t ok = (gl >= 0 && gl < LSEQ) ? 16u : 0u;
        int glc = gl < 0 ? 0 : (gl > LSEQ - 1 ? LSEQ - 1 : gl);
        size_t so = ((size_t)b * LSEQ + glc) * 512 + ci0 + seg * 8;
        uint32_t d0 = bw + (5120 + l * 20 + seg * 4) * 4;
        CPA_Z(d0, (const char*)XT_HI + so * 2, ok);
        CPA_Z(d0 + 5120, (const char*)XT_LO + so * 2, ok);
    }
}

__global__ void __launch_bounds__(256) conv_qkv_mma(
    const float* __restrict__ bb0, const float* __restrict__ bb1,
    const float* __restrict__ bb2)
{
    extern __shared__ uint32_t cbuf[];
    const uint32_t smb = smem_u32(cbuf);

    const int c = blockIdx.z % 3;
    const int b = blockIdx.z / 3;
    const float* bias = (c == 0) ? bb0 : (c == 1) ? bb1 : bb2;
    float* y          = (c == 0) ? g_q : (c == 1) ? g_k : g_v;
    const __nv_bfloat16* whi = W_HI + (size_t)c * 786432;
    const __nv_bfloat16* wlo = W_LO + (size_t)c * 786432;

    const int co0 = blockIdx.y * 128;
    const int l0  = blockIdx.x * 64;
    const int tid = threadIdx.x;
    const int wid = tid >> 5, lane = tid & 31;
    const int wm = wid >> 2, wn = wid & 3;
    const int g = lane >> 2, t4 = lane & 3;

    float acc[4][2][4];
#pragma unroll
    for (int mt = 0; mt < 4; mt++)
#pragma unroll
        for (int nt = 0; nt < 2; nt++)
#pragma unroll
            for (int q = 0; q < 4; q++) acc[mt][nt][q] = 0.f;

    conv_fill(smb, 0, 0, co0, l0, b, tid, whi, wlo);
    CPC();

    for (int ch = 0; ch < 48; ch++) {
        CPW0();
        __syncthreads();
        if (ch + 1 < 48) {
            conv_fill(smb, (ch + 1) & 1, ch + 1, co0, l0, b, tid, whi, wlo);
            CPC();
        }
        const uint32_t* ash = cbuf + (ch & 1) * 7680;
        const uint32_t* bsh = ash + 5120;

#pragma unroll
        for (int ks = 0; ks < 2; ks++) {
            uint32_t Ah[4][4], Al[4][4], Bh[2][2], Bl[2][2];
#pragma unroll
            for (int mt = 0; mt < 4; mt++) {
                int r0 = (wm * 64 + mt * 16 + g) * 20 + ks * 8 + t4;
                int r1 = r0 + 160;
                Ah[mt][0] = ash[r0];     Ah[mt][1] = ash[r1];
                Ah[mt][2] = ash[r0 + 4]; Ah[mt][3] = ash[r1 + 4];
                Al[mt][0] = ash[2560 + r0];     Al[mt][1] = ash[2560 + r1];
                Al[mt][2] = ash[2560 + r0 + 4]; Al[mt][3] = ash[2560 + r1 + 4];
            }
#pragma unroll
            for (int nt = 0; nt < 2; nt++) {
                int c0w = (wn * 16 + nt * 8 + g) * 20 + ks * 8 + t4;
                Bh[nt][0] = bsh[c0w]; Bh[nt][1] = bsh[c0w + 4];
                Bl[nt][0] = bsh[1280 + c0w]; Bl[nt][1] = bsh[1280 + c0w + 4];
            }
#pragma unroll
            for (int mt = 0; mt < 4; mt++)
#pragma unroll
                for (int nt = 0; nt < 2; nt++) {
                    mma_bf16(acc[mt][nt], Ah[mt], Bh[nt]);
                    mma_bf16(acc[mt][nt], Ah[mt], Bl[nt]);
                    mma_bf16(acc[mt][nt], Al[mt], Bh[nt]);
                }
        }
    }

#pragma unroll
    for (int mt = 0; mt < 4; mt++) {
        int co = co0 + wm * 64 + mt * 16 + g;
        float bv0 = bias[co], bv1 = bias[co + 8];
#pragma unroll
        for (int nt = 0; nt < 2; nt++) {
            int lc = l0 + wn * 16 + nt * 8 + t4 * 2;
            size_t o0 = ((size_t)b * 512 + co) * LSEQ + lc;
            float2 v0 = make_float2(acc[mt][nt][0] + bv0, acc[mt][nt][1] + bv0);
            float2 v1 = make_float2(acc[mt][nt][2] + bv1, acc[mt][nt][3] + bv1);
            *(float2*)&y[o0]            = v0;
            *(float2*)&y[o0 + 8 * LSEQ] = v1;
        }
    }
}

// ---------------------------------------------------------------------------
// Flash attention on HMMA — R13 verbatim (proven 1681us total).
// ---------------------------------------------------------------------------
#define PW 36   // row pitch in words (72 bf16)

__global__ void __launch_bounds__(256, 2) attn_tc(float* __restrict__ out)
{
    extern __shared__ char smc[];
    uint32_t* qsh = (uint32_t*)(smc);
    uint32_t* qsl = (uint32_t*)(smc + 18432);
    uint32_t* ksh = (uint32_t*)(smc + 36864);
    uint32_t* ksl = (uint32_t*)(smc + 46080);
    uint32_t* vsh = (uint32_t*)(smc + 55296);
    uint32_t* vsl = (uint32_t*)(smc + 64512);
    float*    osf = (float*)(smc + 36864);

    const int bh  = blockIdx.y;
    const int i0  = blockIdx.x * 128;
    const int tid = threadIdx.x;
    const int w   = tid >> 5;
    const int lane = tid & 31;
    const int g   = lane >> 2, t4 = lane & 3;
    const size_t base = (size_t)bh * 64 * LSEQ;

    {
        int i = tid >> 1;
        int s = (tid & 1) * 4;
        const uint32_t* qh = (const uint32_t*)QT_HI +
            ((size_t)bh * LSEQ + i0 + i) * 32;
        const uint32_t* ql = (const uint32_t*)QT_LO +
            ((size_t)bh * LSEQ + i0 + i) * 32;
#pragma unroll
        for (int q = 0; q < 4; q++) {
            *(uint4*)&qsh[i * PW + (s + q) * 4] = *(const uint4*)(qh + (s + q) * 4);
            *(uint4*)&qsl[i * PW + (s + q) * 4] = *(const uint4*)(ql + (s + q) * 4);
        }
    }

    float oacc[8][4];
#pragma unroll
    for (int nt = 0; nt < 8; nt++)
#pragma unroll
        for (int q = 0; q < 4; q++) oacc[nt][q] = 0.f;
    float m0r = -1e30f, m1r = -1e30f, l0r = 0.f, l1r = 0.f;

    const int fr = tid >> 2;
    const int fc = (tid & 3) * 2;

    for (int m0 = 0; m0 < LSEQ; m0 += 64) {
        __syncthreads();
        {
            const uint32_t* kh = (const uint32_t*)KT_HI +
                ((size_t)bh * LSEQ + m0 + fr) * 32;
            const uint32_t* kl = (const uint32_t*)KT_LO +
                ((size_t)bh * LSEQ + m0 + fr) * 32;
            *(uint4*)&ksh[fr * PW + fc * 4]       = *(const uint4*)(kh + fc * 4);
            *(uint4*)&ksh[fr * PW + (fc + 1) * 4] = *(const uint4*)(kh + (fc + 1) * 4);
            *(uint4*)&ksl[fr * PW + fc * 4]       = *(const uint4*)(kl + fc * 4);
            *(uint4*)&ksl[fr * PW + (fc + 1) * 4] = *(const uint4*)(kl + (fc + 1) * 4);
            const uint32_t* vh = (const uint32_t*)VT_HI +
                ((size_t)bh * 64 + fr) * 1024 + m0 / 2;
            const uint32_t* vl = (const uint32_t*)VT_LO +
                ((size_t)bh * 64 + fr) * 1024 + m0 / 2;
            *(uint4*)&vsh[fr * PW + fc * 4]       = *(const uint4*)(vh + fc * 4);
            *(uint4*)&vsh[fr * PW + (fc + 1) * 4] = *(const uint4*)(vh + (fc + 1) * 4);
            *(uint4*)&vsl[fr * PW + fc * 4]       = *(const uint4*)(vl + fc * 4);
            *(uint4*)&vsl[fr * PW + (fc + 1) * 4] = *(const uint4*)(vl + (fc + 1) * 4);
        }
        __syncthreads();

        float sa[8][4];
#pragma unroll
        for (int nt = 0; nt < 8; nt++)
#pragma unroll
            for (int q = 0; q < 4; q++) sa[nt][q] = 0.f;

#pragma unroll
        for (int ks = 0; ks < 4; ks++) {
            uint32_t ah[4], al[4];
            int ra = (w * 16 + g) * PW + ks * 8 + t4;
            ah[0] = qsh[ra]; ah[1] = qsh[ra + 8 * PW];
            ah[2] = qsh[ra + 4]; ah[3] = qsh[ra + 8 * PW + 4];
            al[0] = qsl[ra]; al[1] = qsl[ra + 8 * PW];
            al[2] = qsl[ra + 4]; al[3] = qsl[ra + 8 * PW + 4];
#pragma unroll
            for (int jt = 0; jt < 8; jt++) {
                uint32_t bhh[2], bll[2];
                int rb = (jt * 8 + g) * PW + ks * 8 + t4;
                bhh[0] = ksh[rb]; bhh[1] = ksh[rb + 4];
                bll[0] = ksl[rb]; bll[1] = ksl[rb + 4];
                mma_bf16(sa[jt], ah, bhh);
                mma_bf16(sa[jt], ah, bll);
                mma_bf16(sa[jt], al, bhh);
            }
        }

        float mn0 = -1e30f, mn1 = -1e30f;
#pragma unroll
        for (int nt = 0; nt < 8; nt++) {
#pragma unroll
            for (int q = 0; q < 4; q++) sa[nt][q] *= ATT_SCALE;
            mn0 = fmaxf(mn0, fmaxf(sa[nt][0], sa[nt][1]));
            mn1 = fmaxf(mn1, fmaxf(sa[nt][2], sa[nt][3]));
        }
        mn0 = fmaxf(mn0, __shfl_xor_sync(0xffffffffu, mn0, 1));
        mn0 = fmaxf(mn0, __shfl_xor_sync(0xffffffffu, mn0, 2));
        mn1 = fmaxf(mn1, __shfl_xor_sync(0xffffffffu, mn1, 1));
        mn1 = fmaxf(mn1, __shfl_xor_sync(0xffffffffu, mn1, 2));

        float mnew0 = fmaxf(m0r, mn0), mnew1 = fmaxf(m1r, mn1);
        float alpha0 = __expf(m0r - mnew0), alpha1 = __expf(m1r - mnew1);
        m0r = mnew0; m1r = mnew1;

        float rs0 = 0.f, rs1 = 0.f;
#pragma unroll
        for (int nt = 0; nt < 8; nt++) {
            sa[nt][0] = __expf(sa[nt][0] - mnew0);
            sa[nt][1] = __expf(sa[nt][1] - mnew0);
            sa[nt][2] = __expf(sa[nt][2] - mnew1);
            sa[nt][3] = __expf(sa[nt][3] - mnew1);
            rs0 += sa[nt][0] + sa[nt][1];
            rs1 += sa[nt][2] + sa[nt][3];
        }
        rs0 += __shfl_xor_sync(0xffffffffu, rs0, 1);
        rs0 += __shfl_xor_sync(0xffffffffu, rs0, 2);
        rs1 += __shfl_xor_sync(0xffffffffu, rs1, 1);
        rs1 += __shfl_xor_sync(0xffffffffu, rs1, 2);
        l0r = l0r * alpha0 + rs0;
        l1r = l1r * alpha1 + rs1;

#pragma unroll
        for (int nt = 0; nt < 8; nt++) {
            oacc[nt][0] *= alpha0; oacc[nt][1] *= alpha0;
            oacc[nt][2] *= alpha1; oacc[nt][3] *= alpha1;
        }

#pragma unroll
        for (int ks = 0; ks < 4; ks++) {
            uint32_t ph[4], pl[4];
            split_pack(sa[2 * ks][1],     sa[2 * ks][0],     ph[0], pl[0]);
            split_pack(sa[2 * ks][3],     sa[2 * ks][2],     ph[1], pl[1]);
            split_pack(sa[2 * ks + 1][1], sa[2 * ks + 1][0], ph[2], pl[2]);
            split_pack(sa[2 * ks + 1][3], sa[2 * ks + 1][2], ph[3], pl[3]);
#pragma unroll
            for (int nt = 0; nt < 8; nt++) {
                uint32_t bhh[2], bll[2];
                int rb = (nt * 8 + g) * PW + ks * 8 + t4;
                bhh[0] = vsh[rb]; bhh[1] = vsh[rb + 4];
                bll[0] = vsl[rb]; bll[1] = vsl[rb + 4];
                mma_bf16(oacc[nt], ph, bhh);
                mma_bf16(oacc[nt], ph, bll);
                mma_bf16(oacc[nt], pl, bhh);
            }
        }
    }

    __syncthreads();
    {
        float inv0 = 1.f / l0r, inv1 = 1.f / l1r;
        int ir0 = w * 16 + g, ir1 = ir0 + 8;
#pragma unroll
        for (int nt = 0; nt < 8; nt++) {
            int d = nt * 8 + 2 * t4;
            osf[d * 132 + ir0]       = oacc[nt][0] * inv0;
            osf[(d + 1) * 132 + ir0] = oacc[nt][1] * inv0;
            osf[d * 132 + ir1]       = oacc[nt][2] * inv1;
            osf[(d + 1) * 132 + ir1] = oacc[nt][3] * inv1;
        }
    }
    __syncthreads();
#pragma unroll
    for (int r = 0; r < 8; r++) {
        int f4 = tid + r * 256;
        int d = f4 >> 5, ig = f4 & 31;
        float4 v = *(const float4*)&osf[d * 132 + ig * 4];
        *(float4*)&out[base + (size_t)d * LSEQ + i0 + ig * 4] = v;
    }
}

// ---------------------------------------------------------------------------
extern "C" void kernel_launch(void* const* d_in, const int* in_sizes, int n_in,
                              void* d_out, int out_size)
{
    const float* x  = (const float*)d_in[0];
    const float* w0 = (const float*)d_in[1];
    const float* b0 = (const float*)d_in[2];
    const float* w1 = (const float*)d_in[3];
    const float* b1 = (const float*)d_in[4];
    const float* w2 = (const float*)d_in[5];
    const float* b2 = (const float*)d_in[6];
    float* out = (float*)d_out;

    // 1) conv operand staging
    dim3 wgrid(786432 / 256, 3);
    split_w_kernel<<<wgrid, 256>>>(w0, w1, w2);
    dim3 xgrid(LSEQ / 32, 16, BATCH);
    split_x_kernel<<<xgrid, 256>>>(x);

    // 2) conv projections (cp.async pipelined — isolated change)
    const int CSMEM = 61440;
    cudaFuncSetAttribute(conv_qkv_mma,
                         cudaFuncAttributeMaxDynamicSharedMemorySize, CSMEM);
    dim3 cgrid(LSEQ / 64, 4, 24);
    conv_qkv_mma<<<cgrid, 256, CSMEM>>>(b0, b1, b2);

    // 3) attention operand staging
    dim3 sgrid(LSEQ / 64, 64, 3);
    stage_qkv_kernel<<<sgrid, 256>>>();

    // 4) attention (R13 verbatim)
    const int ASMEM = 73728;
    cudaFuncSetAttribute(attn_tc,
                         cudaFuncAttributeMaxDynamicSharedMemorySize, ASMEM);
    dim3 agrid(16, 64);
    attn_tc<<<agrid, 256, ASMEM>>>(out);
}

// round 16
// speedup vs baseline: 1.7059x; 1.0886x over previous
#include <cuda_runtime.h>
#include <cuda_bf16.h>
#include <cstdint>

#define LSEQ 2048
#define BATCH 8
// 1/sqrt(512)
#define ATT_SCALE 0.044194173824159216f

// fp32 conv outputs
__device__ float g_q[BATCH * 512 * LSEQ];
__device__ float g_k[BATCH * 512 * LSEQ];
__device__ float g_v[BATCH * 512 * LSEQ];
// conv operand staging (split bf16)
__device__ uint4 g_w_hi4[3 * 512 * 1536 / 8];      // [conv][co][k][ci]
__device__ uint4 g_w_lo4[3 * 512 * 1536 / 8];
__device__ uint4 g_xt_hi4[BATCH * LSEQ * 512 / 8]; // [b][l][ci]
__device__ uint4 g_xt_lo4[BATCH * LSEQ * 512 / 8];
// attention operand staging (split bf16)
__device__ uint4 g_qt_hi4[64 * LSEQ * 64 / 8];     // [bh][l][d]
__device__ uint4 g_qt_lo4[64 * LSEQ * 64 / 8];
__device__ uint4 g_kt_hi4[64 * LSEQ * 64 / 8];     // [bh][l][d]
__device__ uint4 g_kt_lo4[64 * LSEQ * 64 / 8];
__device__ uint4 g_vt_hi4[64 * 64 * LSEQ / 8];     // [bh][d][l]
__device__ uint4 g_vt_lo4[64 * 64 * LSEQ / 8];
#define W_HI ((__nv_bfloat16*)g_w_hi4)
#define W_LO ((__nv_bfloat16*)g_w_lo4)
#define XT_HI ((__nv_bfloat16*)g_xt_hi4)
#define XT_LO ((__nv_bfloat16*)g_xt_lo4)
#define QT_HI ((__nv_bfloat16*)g_qt_hi4)
#define QT_LO ((__nv_bfloat16*)g_qt_lo4)
#define KT_HI ((__nv_bfloat16*)g_kt_hi4)
#define KT_LO ((__nv_bfloat16*)g_kt_lo4)
#define VT_HI ((__nv_bfloat16*)g_vt_hi4)
#define VT_LO ((__nv_bfloat16*)g_vt_lo4)

__device__ __forceinline__ uint32_t smem_u32(const void* p) {
    uint32_t a;
    asm("{ .reg .u64 t; cvta.to.shared.u64 t, %1; cvt.u32.u64 %0, t; }"
        : "=r"(a) : "l"(p));
    return a;
}
#define CPA(dst, src) \
    asm volatile("cp.async.ca.shared.global [%0], [%1], 16;" \
                 :: "r"(dst), "l"(src))
#define CPA_Z(dst, src, sz) \
    asm volatile("cp.async.ca.shared.global [%0], [%1], 16, %2;" \
                 :: "r"(dst), "l"(src), "r"(sz))
#define CPC()  asm volatile("cp.async.commit_group;")
#define CPW0() asm volatile("cp.async.wait_group 0;")

#define LDSM4(r0, r1, r2, r3, addr) \
    asm volatile("ldmatrix.sync.aligned.m8n8.x4.shared.b16 {%0,%1,%2,%3}, [%4];" \
                 : "=r"(r0), "=r"(r1), "=r"(r2), "=r"(r3) : "r"(addr))
#define LDSM2(r0, r1, addr) \
    asm volatile("ldmatrix.sync.aligned.m8n8.x2.shared.b16 {%0,%1}, [%2];" \
                 : "=r"(r0), "=r"(r1) : "r"(addr))

__device__ __forceinline__ void split2(float f, __nv_bfloat16& h, __nv_bfloat16& l) {
    h = __float2bfloat16_rn(f);
    l = __float2bfloat16_rn(f - __bfloat162float(h));
}
__device__ __forceinline__ uint32_t cvt_bf16x2(float f1, float f0) {
    uint32_t r;
    asm("cvt.rn.bf16x2.f32 %0, %1, %2;" : "=r"(r) : "f"(f1), "f"(f0));
    return r;
}
__device__ __forceinline__ void split_pack(float f1, float f0,
                                           uint32_t& h, uint32_t& l) {
    h = cvt_bf16x2(f1, f0);
    float h0 = __uint_as_float(h << 16);
    float h1 = __uint_as_float(h & 0xffff0000u);
    l = cvt_bf16x2(f1 - h1, f0 - h0);
}
__device__ __forceinline__ void mma_bf16(float acc[4], const uint32_t a[4],
                                         const uint32_t b[2])
{
    asm volatile(
        "mma.sync.aligned.m16n8k16.row.col.f32.bf16.bf16.f32 "
        "{%0,%1,%2,%3}, {%4,%5,%6,%7}, {%8,%9}, {%0,%1,%2,%3};\n"
        : "+f"(acc[0]), "+f"(acc[1]), "+f"(acc[2]), "+f"(acc[3])
        : "r"(a[0]), "r"(a[1]), "r"(a[2]), "r"(a[3]), "r"(b[0]), "r"(b[1]));
}

// ---------------------------------------------------------------------------
// w[co][ci][k] fp32 -> w_hi/lo[conv][co][k][ci] bf16
// ---------------------------------------------------------------------------
__global__ void __launch_bounds__(256) split_w_kernel(
    const float* __restrict__ w0, const float* __restrict__ w1,
    const float* __restrict__ w2)
{
    const int conv = blockIdx.y;
    const float* w = (conv == 0) ? w0 : (conv == 1) ? w1 : w2;
    int idx = blockIdx.x * 256 + threadIdx.x;
    int co = idx / 1536, r = idx - co * 1536;
    int kk = r >> 9, ci = r & 511;
    float f = w[(size_t)co * 1536 + ci * 3 + kk];
    __nv_bfloat16 h, l;
    split2(f, h, l);
    size_t o = (size_t)conv * 786432 + idx;
    W_HI[o] = h;
    W_LO[o] = l;
}

// ---------------------------------------------------------------------------
// x[b][ci][l] fp32 -> xt_hi/lo[b][l][ci] bf16, 32x32 smem transpose
// ---------------------------------------------------------------------------
__global__ void __launch_bounds__(256) split_x_kernel(const float* __restrict__ x)
{
    __shared__ float t[32][33];
    const int b = blockIdx.z, c0 = blockIdx.y * 32, l0 = blockIdx.x * 32;
    const int tx = threadIdx.x & 31, ty = threadIdx.x >> 5;
#pragma unroll
    for (int r = 0; r < 32; r += 8)
        t[ty + r][tx] = x[((size_t)b * 512 + c0 + ty + r) * LSEQ + l0 + tx];
    __syncthreads();
#pragma unroll
    for (int r = 0; r < 32; r += 8) {
        float v = t[tx][ty + r];
        __nv_bfloat16 h, l;
        split2(v, h, l);
        size_t o = ((size_t)b * LSEQ + l0 + ty + r) * 512 + c0 + tx;
        XT_HI[o] = h;
        XT_LO[o] = l;
    }
}

// ---------------------------------------------------------------------------
// Stage q/k/v fp32 -> attention layouts (split bf16), proven.
// ---------------------------------------------------------------------------
__global__ void __launch_bounds__(256) stage_qkv_kernel()
{
    const int z  = blockIdx.z;
    const int bh = blockIdx.y;
    const int l0 = blockIdx.x * 64;
    const int tid = threadIdx.x;
    const float* src = (z == 0) ? g_q : (z == 1) ? g_k : g_v;
    const size_t base = (size_t)bh * 64 * LSEQ;

    if (z < 2) {
        __shared__ float t[64][65];
        __nv_bfloat16* dh = (z == 0) ? QT_HI : KT_HI;
        __nv_bfloat16* dl = (z == 0) ? QT_LO : KT_LO;
        int d  = tid >> 2;
        int ls = (tid & 3) * 16;
#pragma unroll
        for (int q = 0; q < 4; q++) {
            float4 v = *(const float4*)&src[base + (size_t)d * LSEQ + l0 + ls + q * 4];
            t[d][ls + q * 4 + 0] = v.x;
            t[d][ls + q * 4 + 1] = v.y;
            t[d][ls + q * 4 + 2] = v.z;
            t[d][ls + q * 4 + 3] = v.w;
        }
        __syncthreads();
        int l  = tid >> 2;
        int ds = (tid & 3) * 16;
        uint32_t hw[8], lw[8];
#pragma unroll
        for (int m = 0; m < 8; m++) {
            float f0 = t[ds + 2 * m][l];
            float f1 = t[ds + 2 * m + 1][l];
            split_pack(f1, f0, hw[m], lw[m]);
        }
        size_t wo = ((size_t)bh * LSEQ + l0 + l) * 32 + ds / 2;
        *(uint4*)((uint32_t*)dh + wo)     = *(uint4*)&hw[0];
        *(uint4*)((uint32_t*)dh + wo + 4) = *(uint4*)&hw[4];
        *(uint4*)((uint32_t*)dl + wo)     = *(uint4*)&lw[0];
        *(uint4*)((uint32_t*)dl + wo + 4) = *(uint4*)&lw[4];
    } else {
        int d  = tid >> 2;
        int ls = (tid & 3) * 16;
        uint32_t hw[8], lw[8];
#pragma unroll
        for (int q = 0; q < 4; q++) {
            float4 v = *(const float4*)&src[base + (size_t)d * LSEQ + l0 + ls + q * 4];
            split_pack(v.y, v.x, hw[q * 2],     lw[q * 2]);
            split_pack(v.w, v.z, hw[q * 2 + 1], lw[q * 2 + 1]);
        }
        size_t wo = ((size_t)bh * 64 + d) * 1024 + (l0 + ls) / 2;
        *(uint4*)((uint32_t*)VT_HI + wo)     = *(uint4*)&hw[0];
        *(uint4*)((uint32_t*)VT_HI + wo + 4) = *(uint4*)&hw[4];
        *(uint4*)((uint32_t*)VT_LO + wo)     = *(uint4*)&lw[0];
        *(uint4*)((uint32_t*)VT_LO + wo + 4) = *(uint4*)&lw[4];
    }
}

// ---------------------------------------------------------------------------
// Conv via HMMA, cp.async double-buffered (R14) + LDSM fragment loads (new).
// Buffer (words): A_hi 0..2560, A_lo ..5120, B_hi ..6400, B_lo ..7680.
// ---------------------------------------------------------------------------
__device__ __forceinline__ void conv_fill(
    uint32_t smb, int bb, int ch, int co0, int l0, int b, int tid,
    const __nv_bfloat16* whi, const __nv_bfloat16* wlo)
{
    const int kk  = ch >> 4;
    const int ci0 = (ch & 15) << 5;
    const uint32_t bw = smb + bb * 7680 * 4;
    {
        int co = tid >> 1, seg = tid & 1;
        const char* sh = (const char*)whi +
            ((size_t)(co0 + co) * 1536 + kk * 512 + ci0 + seg * 16) * 2;
        const char* sl = (const char*)wlo +
            ((size_t)(co0 + co) * 1536 + kk * 512 + ci0 + seg * 16) * 2;
        uint32_t d0 = bw + (co * 20 + seg * 8) * 4;
        CPA(d0, sh);          CPA(d0 + 16, sh + 16);
        CPA(d0 + 10240, sl);  CPA(d0 + 10240 + 16, sl + 16);
    }
    {
        int l = tid >> 2, seg = tid & 3;
        int gl = l0 + l + kk - 1;
        uint32_t ok = (gl >= 0 && gl < LSEQ) ? 16u : 0u;
        int glc = gl < 0 ? 0 : (gl > LSEQ - 1 ? LSEQ - 1 : gl);
        size_t so = ((size_t)b * LSEQ + glc) * 512 + ci0 + seg * 8;
        uint32_t d0 = bw + (5120 + l * 20 + seg * 4) * 4;
        CPA_Z(d0, (const char*)XT_HI + so * 2, ok);
        CPA_Z(d0 + 5120, (const char*)XT_LO + so * 2, ok);
    }
}

__global__ void __launch_bounds__(256) conv_qkv_mma(
    const float* __restrict__ bb0, const float* __restrict__ bb1,
    const float* __restrict__ bb2)
{
    extern __shared__ uint32_t cbuf[];
    const uint32_t smb = smem_u32(cbuf);

    const int c = blockIdx.z % 3;
    const int b = blockIdx.z / 3;
    const float* bias = (c == 0) ? bb0 : (c == 1) ? bb1 : bb2;
    float* y          = (c == 0) ? g_q : (c == 1) ? g_k : g_v;
    const __nv_bfloat16* whi = W_HI + (size_t)c * 786432;
    const __nv_bfloat16* wlo = W_LO + (size_t)c * 786432;

    const int co0 = blockIdx.y * 128;
    const int l0  = blockIdx.x * 64;
    const int tid = threadIdx.x;
    const int wid = tid >> 5, lane = tid & 31;
    const int wm = wid >> 2, wn = wid & 3;
    const int g = lane >> 2, t4 = lane & 3;

    // LDSM per-lane source addresses (bytes), buffer 0:
    //  A x4: row = wm*64 + (lane&15), 16B chunk = lane>>4
    //  B x2: row = wn*16 + (lane&7),  16B chunk = (lane>>3)&1
    const uint32_t a_base = smb +
        ((wm * 64 + (lane & 15)) * 20 + (lane >> 4) * 4) * 4;
    const uint32_t b_base = smb + 20480 +
        ((wn * 16 + (lane & 7)) * 20 + ((lane >> 3) & 1) * 4) * 4;

    float acc[4][2][4];
#pragma unroll
    for (int mt = 0; mt < 4; mt++)
#pragma unroll
        for (int nt = 0; nt < 2; nt++)
#pragma unroll
            for (int q = 0; q < 4; q++) acc[mt][nt][q] = 0.f;

    conv_fill(smb, 0, 0, co0, l0, b, tid, whi, wlo);
    CPC();

    for (int ch = 0; ch < 48; ch++) {
        CPW0();
        __syncthreads();
        if (ch + 1 < 48) {
            conv_fill(smb, (ch + 1) & 1, ch + 1, co0, l0, b, tid, whi, wlo);
            CPC();
        }
        const uint32_t boff = (ch & 1) * 30720;   // bytes

#pragma unroll
        for (int ks = 0; ks < 2; ks++) {
            uint32_t Ah[4][4], Al[4][4], Bh[2][2], Bl[2][2];
            const uint32_t koff = boff + ks * 32;   // ks*8 words
#pragma unroll
            for (int mt = 0; mt < 4; mt++) {
                uint32_t aa = a_base + koff + mt * 1280;   // mt*16 rows * 80B
                LDSM4(Ah[mt][0], Ah[mt][1], Ah[mt][2], Ah[mt][3], aa);
                LDSM4(Al[mt][0], Al[mt][1], Al[mt][2], Al[mt][3], aa + 10240);
            }
#pragma unroll
            for (int nt = 0; nt < 2; nt++) {
                uint32_t ba = b_base + koff + nt * 640;    // nt*8 rows * 80B
                LDSM2(Bh[nt][0], Bh[nt][1], ba);
                LDSM2(Bl[nt][0], Bl[nt][1], ba + 5120);
            }
#pragma unroll
            for (int mt = 0; mt < 4; mt++)
#pragma unroll
                for (int nt = 0; nt < 2; nt++) {
                    mma_bf16(acc[mt][nt], Ah[mt], Bh[nt]);
                    mma_bf16(acc[mt][nt], Ah[mt], Bl[nt]);
                    mma_bf16(acc[mt][nt], Al[mt], Bh[nt]);
                }
        }
    }

#pragma unroll
    for (int mt = 0; mt < 4; mt++) {
        int co = co0 + wm * 64 + mt * 16 + g;
        float bv0 = bias[co], bv1 = bias[co + 8];
#pragma unroll
        for (int nt = 0; nt < 2; nt++) {
            int lc = l0 + wn * 16 + nt * 8 + t4 * 2;
            size_t o0 = ((size_t)b * 512 + co) * LSEQ + lc;
            float2 v0 = make_float2(acc[mt][nt][0] + bv0, acc[mt][nt][1] + bv0);
            float2 v1 = make_float2(acc[mt][nt][2] + bv1, acc[mt][nt][3] + bv1);
            *(float2*)&y[o0]            = v0;
            *(float2*)&y[o0 + 8 * LSEQ] = v1;
        }
    }
}

// ---------------------------------------------------------------------------
// Flash attention on HMMA — R13 verbatim (proven).
// ---------------------------------------------------------------------------
#define PW 36   // row pitch in words (72 bf16)

__global__ void __launch_bounds__(256, 2) attn_tc(float* __restrict__ out)
{
    extern __shared__ char smc[];
    uint32_t* qsh = (uint32_t*)(smc);
    uint32_t* qsl = (uint32_t*)(smc + 18432);
    uint32_t* ksh = (uint32_t*)(smc + 36864);
    uint32_t* ksl = (uint32_t*)(smc + 46080);
    uint32_t* vsh = (uint32_t*)(smc + 55296);
    uint32_t* vsl = (uint32_t*)(smc + 64512);
    float*    osf = (float*)(smc + 36864);

    const int bh  = blockIdx.y;
    const int i0  = blockIdx.x * 128;
    const int tid = threadIdx.x;
    const int w   = tid >> 5;
    const int lane = tid & 31;
    const int g   = lane >> 2, t4 = lane & 3;
    const size_t base = (size_t)bh * 64 * LSEQ;

    {
        int i = tid >> 1;
        int s = (tid & 1) * 4;
        const uint32_t* qh = (const uint32_t*)QT_HI +
            ((size_t)bh * LSEQ + i0 + i) * 32;
        const uint32_t* ql = (const uint32_t*)QT_LO +
            ((size_t)bh * LSEQ + i0 + i) * 32;
#pragma unroll
        for (int q = 0; q < 4; q++) {
            *(uint4*)&qsh[i * PW + (s + q) * 4] = *(const uint4*)(qh + (s + q) * 4);
            *(uint4*)&qsl[i * PW + (s + q) * 4] = *(const uint4*)(ql + (s + q) * 4);
        }
    }

    float oacc[8][4];
#pragma unroll
    for (int nt = 0; nt < 8; nt++)
#pragma unroll
        for (int q = 0; q < 4; q++) oacc[nt][q] = 0.f;
    float m0r = -1e30f, m1r = -1e30f, l0r = 0.f, l1r = 0.f;

    const int fr = tid >> 2;
    const int fc = (tid & 3) * 2;

    for (int m0 = 0; m0 < LSEQ; m0 += 64) {
        __syncthreads();
        {
            const uint32_t* kh = (const uint32_t*)KT_HI +
                ((size_t)bh * LSEQ + m0 + fr) * 32;
            const uint32_t* kl = (const uint32_t*)KT_LO +
                ((size_t)bh * LSEQ + m0 + fr) * 32;
            *(uint4*)&ksh[fr * PW + fc * 4]       = *(const uint4*)(kh + fc * 4);
            *(uint4*)&ksh[fr * PW + (fc + 1) * 4] = *(const uint4*)(kh + (fc + 1) * 4);
            *(uint4*)&ksl[fr * PW + fc * 4]       = *(const uint4*)(kl + fc * 4);
            *(uint4*)&ksl[fr * PW + (fc + 1) * 4] = *(const uint4*)(kl + (fc + 1) * 4);
            const uint32_t* vh = (const uint32_t*)VT_HI +
                ((size_t)bh * 64 + fr) * 1024 + m0 / 2;
            const uint32_t* vl = (const uint32_t*)VT_LO +
                ((size_t)bh * 64 + fr) * 1024 + m0 / 2;
            *(uint4*)&vsh[fr * PW + fc * 4]       = *(const uint4*)(vh + fc * 4);
            *(uint4*)&vsh[fr * PW + (fc + 1) * 4] = *(const uint4*)(vh + (fc + 1) * 4);
            *(uint4*)&vsl[fr * PW + fc * 4]       = *(const uint4*)(vl + fc * 4);
            *(uint4*)&vsl[fr * PW + (fc + 1) * 4] = *(const uint4*)(vl + (fc + 1) * 4);
        }
        __syncthreads();

        float sa[8][4];
#pragma unroll
        for (int nt = 0; nt < 8; nt++)
#pragma unroll
            for (int q = 0; q < 4; q++) sa[nt][q] = 0.f;

#pragma unroll
        for (int ks = 0; ks < 4; ks++) {
            uint32_t ah[4], al[4];
            int ra = (w * 16 + g) * PW + ks * 8 + t4;
            ah[0] = qsh[ra]; ah[1] = qsh[ra + 8 * PW];
            ah[2] = qsh[ra + 4]; ah[3] = qsh[ra + 8 * PW + 4];
            al[0] = qsl[ra]; al[1] = qsl[ra + 8 * PW];
            al[2] = qsl[ra + 4]; al[3] = qsl[ra + 8 * PW + 4];
#pragma unroll
            for (int jt = 0; jt < 8; jt++) {
                uint32_t bhh[2], bll[2];
                int rb = (jt * 8 + g) * PW + ks * 8 + t4;
                bhh[0] = ksh[rb]; bhh[1] = ksh[rb + 4];
                bll[0] = ksl[rb]; bll[1] = ksl[rb + 4];
                mma_bf16(sa[jt], ah, bhh);
                mma_bf16(sa[jt], ah, bll);
                mma_bf16(sa[jt], al, bhh);
            }
        }

        float mn0 = -1e30f, mn1 = -1e30f;
#pragma unroll
        for (int nt = 0; nt < 8; nt++) {
#pragma unroll
            for (int q = 0; q < 4; q++) sa[nt][q] *= ATT_SCALE;
            mn0 = fmaxf(mn0, fmaxf(sa[nt][0], sa[nt][1]));
            mn1 = fmaxf(mn1, fmaxf(sa[nt][2], sa[nt][3]));
        }
        mn0 = fmaxf(mn0, __shfl_xor_sync(0xffffffffu, mn0, 1));
        mn0 = fmaxf(mn0, __shfl_xor_sync(0xffffffffu, mn0, 2));
        mn1 = fmaxf(mn1, __shfl_xor_sync(0xffffffffu, mn1, 1));
        mn1 = fmaxf(mn1, __shfl_xor_sync(0xffffffffu, mn1, 2));

        float mnew0 = fmaxf(m0r, mn0), mnew1 = fmaxf(m1r, mn1);
        float alpha0 = __expf(m0r - mnew0), alpha1 = __expf(m1r - mnew1);
        m0r = mnew0; m1r = mnew1;

        float rs0 = 0.f, rs1 = 0.f;
#pragma unroll
        for (int nt = 0; nt < 8; nt++) {
            sa[nt][0] = __expf(sa[nt][0] - mnew0);
            sa[nt][1] = __expf(sa[nt][1] - mnew0);
            sa[nt][2] = __expf(sa[nt][2] - mnew1);
            sa[nt][3] = __expf(sa[nt][3] - mnew1);
            rs0 += sa[nt][0] + sa[nt][1];
            rs1 += sa[nt][2] + sa[nt][3];
        }
        rs0 += __shfl_xor_sync(0xffffffffu, rs0, 1);
        rs0 += __shfl_xor_sync(0xffffffffu, rs0, 2);
        rs1 += __shfl_xor_sync(0xffffffffu, rs1, 1);
        rs1 += __shfl_xor_sync(0xffffffffu, rs1, 2);
        l0r = l0r * alpha0 + rs0;
        l1r = l1r * alpha1 + rs1;

#pragma unroll
        for (int nt = 0; nt < 8; nt++) {
            oacc[nt][0] *= alpha0; oacc[nt][1] *= alpha0;
            oacc[nt][2] *= alpha1; oacc[nt][3] *= alpha1;
        }

#pragma unroll
        for (int ks = 0; ks < 4; ks++) {
            uint32_t ph[4], pl[4];
            split_pack(sa[2 * ks][1],     sa[2 * ks][0],     ph[0], pl[0]);
            split_pack(sa[2 * ks][3],     sa[2 * ks][2],     ph[1], pl[1]);
            split_pack(sa[2 * ks + 1][1], sa[2 * ks + 1][0], ph[2], pl[2]);
            split_pack(sa[2 * ks + 1][3], sa[2 * ks + 1][2], ph[3], pl[3]);
#pragma unroll
            for (int nt = 0; nt < 8; nt++) {
                uint32_t bhh[2], bll[2];
                int rb = (nt * 8 + g) * PW + ks * 8 + t4;
                bhh[0] = vsh[rb]; bhh[1] = vsh[rb + 4];
                bll[0] = vsl[rb]; bll[1] = vsl[rb + 4];
                mma_bf16(oacc[nt], ph, bhh);
                mma_bf16(oacc[nt], ph, bll);
                mma_bf16(oacc[nt], pl, bhh);
            }
        }
    }

    __syncthreads();
    {
        float inv0 = 1.f / l0r, inv1 = 1.f / l1r;
        int ir0 = w * 16 + g, ir1 = ir0 + 8;
#pragma unroll
        for (int nt = 0; nt < 8; nt++) {
            int d = nt * 8 + 2 * t4;
            osf[d * 132 + ir0]       = oacc[nt][0] * inv0;
            osf[(d + 1) * 132 + ir0] = oacc[nt][1] * inv0;
            osf[d * 132 + ir1]       = oacc[nt][2] * inv1;
            osf[(d + 1) * 132 + ir1] = oacc[nt][3] * inv1;
        }
    }
    __syncthreads();
#pragma unroll
    for (int r = 0; r < 8; r++) {
        int f4 = tid + r * 256;
        int d = f4 >> 5, ig = f4 & 31;
        float4 v = *(const float4*)&osf[d * 132 + ig * 4];
        *(float4*)&out[base + (size_t)d * LSEQ + i0 + ig * 4] = v;
    }
}

// ---------------------------------------------------------------------------
extern "C" void kernel_launch(void* const* d_in, const int* in_sizes, int n_in,
                              void* d_out, int out_size)
{
    const float* x  = (const float*)d_in[0];
    const float* w0 = (const float*)d_in[1];
    const float* b0 = (const float*)d_in[2];
    const float* w1 = (const float*)d_in[3];
    const float* b1 = (const float*)d_in[4];
    const float* w2 = (const float*)d_in[5];
    const float* b2 = (const float*)d_in[6];
    float* out = (float*)d_out;

    // 1) conv operand staging
    dim3 wgrid(786432 / 256, 3);
    split_w_kernel<<<wgrid, 256>>>(w0, w1, w2);
    dim3 xgrid(LSEQ / 32, 16, BATCH);
    split_x_kernel<<<xgrid, 256>>>(x);

    // 2) conv projections (cp.async + LDSM)
    const int CSMEM = 61440;
    cudaFuncSetAttribute(conv_qkv_mma,
                         cudaFuncAttributeMaxDynamicSharedMemorySize, CSMEM);
    dim3 cgrid(LSEQ / 64, 4, 24);
    conv_qkv_mma<<<cgrid, 256, CSMEM>>>(b0, b1, b2);

    // 3) attention operand staging
    dim3 sgrid(LSEQ / 64, 64, 3);
    stage_qkv_kernel<<<sgrid, 256>>>();

    // 4) attention (R13 verbatim)
    const int ASMEM = 73728;
    cudaFuncSetAttribute(attn_tc,
                         cudaFuncAttributeMaxDynamicSharedMemorySize, ASMEM);
    dim3 agrid(16, 64);
    attn_tc<<<agrid, 256, ASMEM>>>(out);
}